// round 9
// baseline (speedup 1.0000x reference)
#include <cuda_runtime.h>
#include <cuda_bf16.h>
#include <math.h>
#include <stdint.h>

// ---------------------------------------------------------------------------
// Problem constants
// ---------------------------------------------------------------------------
constexpr int BATCH = 16;
constexpr int HH    = 56;
constexpr int WWID  = 56;
constexpr int CDIM  = 384;
constexpr int NHEAD = 12;
constexpr int WSZ   = 7;
constexpr int SHIFT = 3;
constexpr int NTOK  = 49;
constexpr int NWIN  = BATCH * 64;
constexpr int TOK   = NWIN * NTOK;        // 50176
constexpr float ATT_SCALE = 0.17677669529663687f;
constexpr float LN_EPS    = 1e-3f;

// ---------------------------------------------------------------------------
// Scratch (device globals)
// ---------------------------------------------------------------------------
__device__ __nv_bfloat16 g_wins[TOK * CDIM];
__device__ float         g_qkv [TOK * 3 * CDIM];
__device__ __nv_bfloat16 g_att [TOK * CDIM];
__device__ float         g_x1  [TOK * CDIM];
__device__ __nv_bfloat16 g_ln2 [TOK * CDIM];
__device__ __nv_bfloat16 g_h   [TOK * 4 * CDIM];
// transposed bf16 weights [N, K]
__device__ __nv_bfloat16 g_wt_qkv [3 * CDIM * CDIM];
__device__ __nv_bfloat16 g_wt_proj[CDIM * CDIM];
__device__ __nv_bfloat16 g_wt_m1  [4 * CDIM * CDIM];
__device__ __nv_bfloat16 g_wt_m2  [4 * CDIM * CDIM];

// ---------------------------------------------------------------------------
// Weight transpose + bf16 convert: W[K,N] fp32 -> WT[N,K] bf16
// ---------------------------------------------------------------------------
__global__ void __launch_bounds__(256)
transpose_w(const float* __restrict__ W, __nv_bfloat16* __restrict__ WT,
            int K, int N)
{
    __shared__ float t[32][33];
    int kb = blockIdx.x * 32, nb = blockIdx.y * 32;
    int x = threadIdx.x & 31, y = threadIdx.x >> 5;   // 32 x 8
    #pragma unroll
    for (int dy = 0; dy < 32; dy += 8)
        t[y + dy][x] = W[(size_t)(kb + y + dy) * N + nb + x];
    __syncthreads();
    #pragma unroll
    for (int dy = 0; dy < 32; dy += 8)
        WT[(size_t)(nb + y + dy) * K + kb + x] = __float2bfloat16(t[x][y + dy]);
}

// ---------------------------------------------------------------------------
// LayerNorm (one block per token), bf16 output.
// gather=1 fuses roll(-3,+3) + window partition.
// ---------------------------------------------------------------------------
__global__ void __launch_bounds__(384)
ln_kernel(const float* __restrict__ X, const float* __restrict__ gam,
          const float* __restrict__ bet, __nv_bfloat16* __restrict__ Y, int gather)
{
    int tok = blockIdx.x;
    int src = tok;
    if (gather) {
        int win = tok / NTOK, n = tok % NTOK;
        int b  = win >> 6, wi = win & 63;
        int wh = wi >> 3,  ww = wi & 7;
        int i  = n / WSZ,  j  = n % WSZ;
        int hs = wh * WSZ + i, ws = ww * WSZ + j;
        int sh = hs + SHIFT; if (sh >= HH)  sh -= HH;
        int sw = ws - SHIFT; if (sw < 0)    sw += WWID;
        src = (b * HH + sh) * WWID + sw;
    }
    int c = threadIdx.x;
    float v = X[(size_t)src * CDIM + c];

    float a = v, b2 = v * v;
    #pragma unroll
    for (int off = 16; off; off >>= 1) {
        a  += __shfl_xor_sync(~0u, a,  off);
        b2 += __shfl_xor_sync(~0u, b2, off);
    }
    __shared__ float s1[12], s2[12];
    __shared__ float mu_s, rs_s;
    int wid = threadIdx.x >> 5, lane = threadIdx.x & 31;
    if (!lane) { s1[wid] = a; s2[wid] = b2; }
    __syncthreads();
    if (threadIdx.x == 0) {
        float sa = 0.f, sb = 0.f;
        #pragma unroll
        for (int k = 0; k < 12; k++) { sa += s1[k]; sb += s2[k]; }
        float mu  = sa / CDIM;
        float var = sb / CDIM - mu * mu;
        mu_s = mu;
        rs_s = rsqrtf(var + LN_EPS);
    }
    __syncthreads();
    Y[(size_t)tok * CDIM + c] =
        __float2bfloat16((v - mu_s) * rs_s * gam[c] + bet[c]);
}

__device__ __forceinline__ int dest_row(int tok)
{
    int win = tok / NTOK, n = tok % NTOK;
    int b  = win >> 6, wi = win & 63;
    int wh = wi >> 3,  ww = wi & 7;
    int i  = n / WSZ,  j  = n % WSZ;
    int hs = wh * WSZ + i, ws = ww * WSZ + j;
    int h = hs + SHIFT; if (h >= HH)   h -= HH;
    int w = ws + SHIFT; if (w >= WWID) w -= WWID;
    return (b * HH + h) * WWID + w;
}

// ---------------------------------------------------------------------------
// bf16 mma.sync GEMM. 256x128 CTA tile, BK=16, 8 warps (64x64 warp tile,
// 4x2 warp grid), m16n8k16 bf16, fp32 accumulation.
// Consumer redundancy: A x2, B x4 (16KB/ktile vs 24KB of the 128x128 shape,
// for 2x the MMA work). Producer & consumer layouts identical to the
// verified round-5/7/8 formulas.
// MODE 0: +bias -> fp32 Cf   MODE 1: +bias,GELU -> bf16 Cb
// MODE 2: +bias,scatter+res -> fp32 Cf   MODE 3: +bias,+res -> fp32 Cf
// Requires M%256==0, N%128==0, K%16==0.
// ---------------------------------------------------------------------------
__device__ __forceinline__ void mma_bf16(float* c, const unsigned* a, const unsigned* b)
{
    asm volatile(
        "mma.sync.aligned.m16n8k16.row.col.f32.bf16.bf16.f32 "
        "{%0,%1,%2,%3}, {%4,%5,%6,%7}, {%8,%9}, {%0,%1,%2,%3};"
        : "+f"(c[0]), "+f"(c[1]), "+f"(c[2]), "+f"(c[3])
        : "r"(a[0]), "r"(a[1]), "r"(a[2]), "r"(a[3]), "r"(b[0]), "r"(b[1]));
}

// SMEM word layouts:
//  A word (m 0..255, kp 0..7):  block = (m>>4)*4 + ((m>>3)&1) + 2*(kp>>2)
//                               slot  = ((m&7)*4 + (kp&3)) ^ ((kp>>2)<<4)
//  B word (kp 0..7, n 0..127):  block = (n>>3)*2 + (kp>>2)
//                               slot  = ((kp&3)*8 + (n&7)) ^ (((n>>3)&3)<<3)
template<int MODE>
__global__ void __launch_bounds__(256)
gemm_tc(const __nv_bfloat16* __restrict__ A, const __nv_bfloat16* __restrict__ Bt,
        const float* __restrict__ bias, const float* __restrict__ res,
        float* __restrict__ Cf, __nv_bfloat16* __restrict__ Cb,
        int M, int N, int K)
{
    __shared__ __align__(16) unsigned As[2][2048];
    __shared__ __align__(16) unsigned Bs[2][1024];

    const int tid  = threadIdx.x;
    const int bm   = blockIdx.y * 256, bn = blockIdx.x * 128;
    const int warp = tid >> 5, lane = tid & 31;
    const int wm   = warp >> 1, wn = warp & 1;       // 4 x 2 warp grid

    // -------- producer mapping --------
    // A: thread -> row ma = tid, loads both k-halves (32B contiguous)
    const int ma = tid;
    const __nv_bfloat16* Ag = A + (size_t)(bm + ma) * K;
    const int aBlk = (ma >> 4) * 4 + ((ma >> 3) & 1);
    const int aAddr0 = aBlk * 32 + (ma & 7) * 4;                  // kp 0..3
    const int aAddr1 = (aBlk + 2) * 32 + (((ma & 7) * 4) ^ 16);   // kp 4..7

    // B: weight row nb = tid>>1, k-half hb = tid&1 (kp = hb*4+0..3)
    const int nb = tid >> 1;
    const int hb = tid & 1;
    const __nv_bfloat16* Bg = Bt + (size_t)(bn + nb) * K + hb * 8;
    int bAddr[4];
    #pragma unroll
    for (int l = 0; l < 4; l++) {
        int kp = hb * 4 + l;
        bAddr[l] = ((nb >> 3) * 2 + (kp >> 2)) * 32
                 + ((((kp & 3) * 8) + (nb & 7)) ^ (((nb >> 3) & 3) << 3));
    }

    uint4 av0, av1, bv;

    #define LOAD_GLB(KT)                                                     \
    {                                                                        \
        av0 = *(const uint4*)(Ag + (KT));                                    \
        av1 = *(const uint4*)(Ag + (KT) + 8);                                \
        bv  = *(const uint4*)(Bg + (KT));                                    \
    }

    #define STORE_SMEM(BUF)                                                  \
    {                                                                        \
        *(uint4*)&As[BUF][aAddr0] = av0;                                     \
        *(uint4*)&As[BUF][aAddr1] = av1;                                     \
        unsigned bw0 = bv.x, bw1 = bv.y, bw2 = bv.z, bw3 = bv.w;             \
        Bs[BUF][bAddr[hb ? 2 : 0]] = hb ? bw2 : bw0;                         \
        Bs[BUF][bAddr[hb ? 3 : 1]] = hb ? bw3 : bw1;                         \
        Bs[BUF][bAddr[hb ? 0 : 2]] = hb ? bw0 : bw2;                         \
        Bs[BUF][bAddr[hb ? 1 : 3]] = hb ? bw1 : bw3;                         \
    }

    float acc[4][8][4];
    #pragma unroll
    for (int i = 0; i < 4; i++)
        #pragma unroll
        for (int j = 0; j < 8; j++)
            #pragma unroll
            for (int r = 0; r < 4; r++) acc[i][j][r] = 0.f;

    const int pbase = (lane & 3) * 8 + (lane >> 2);   // B consumer lane perm

    LOAD_GLB(0)
    STORE_SMEM(0)
    int buf = 0;

    for (int kt = 16; ; kt += 16) {
        __syncthreads();
        bool more = kt < K;
        if (more) LOAD_GLB(kt)

        unsigned afr[4][4], bfr[8][2];
        #pragma unroll
        for (int i = 0; i < 4; i++) {
            int blk = (wm * 4 + i) * 4;
            afr[i][0] = As[buf][(blk + 0) * 32 + lane];
            afr[i][1] = As[buf][(blk + 1) * 32 + lane];
            afr[i][2] = As[buf][(blk + 2) * 32 + (lane ^ 16)];
            afr[i][3] = As[buf][(blk + 3) * 32 + (lane ^ 16)];
        }
        #pragma unroll
        for (int jj = 0; jj < 8; jj++) {
            int blk = (wn * 8 + jj) * 2;
            int sl  = pbase ^ ((jj & 3) << 3);
            bfr[jj][0] = Bs[buf][blk * 32 + sl];
            bfr[jj][1] = Bs[buf][(blk + 1) * 32 + sl];
        }
        #pragma unroll
        for (int i = 0; i < 4; i++)
            #pragma unroll
            for (int jj = 0; jj < 8; jj++)
                mma_bf16(acc[i][jj], afr[i], bfr[jj]);

        if (!more) break;
        STORE_SMEM(buf ^ 1)
        buf ^= 1;
    }
    #undef LOAD_GLB
    #undef STORE_SMEM

    // ---- epilogue: warp owns rows wm*64..+63, cols wn*64..+63 ----
    const int g = lane >> 2, t = lane & 3;
    #pragma unroll
    for (int i = 0; i < 4; i++) {
        int r0 = bm + wm * 64 + i * 16 + g;
        int r1 = r0 + 8;
        int d0 = (MODE == 2) ? dest_row(r0) : r0;
        int d1 = (MODE == 2) ? dest_row(r1) : r1;
        #pragma unroll
        for (int jj = 0; jj < 8; jj++) {
            int col = bn + wn * 64 + jj * 8 + t * 2;
            float bc0 = bias[col], bc1 = bias[col + 1];
            float v00 = acc[i][jj][0] + bc0;
            float v01 = acc[i][jj][1] + bc1;
            float v10 = acc[i][jj][2] + bc0;
            float v11 = acc[i][jj][3] + bc1;
            if (MODE == 1) {
                v00 = 0.5f * v00 * (1.0f + erff(v00 * 0.70710678118654752f));
                v01 = 0.5f * v01 * (1.0f + erff(v01 * 0.70710678118654752f));
                v10 = 0.5f * v10 * (1.0f + erff(v10 * 0.70710678118654752f));
                v11 = 0.5f * v11 * (1.0f + erff(v11 * 0.70710678118654752f));
                __nv_bfloat162 p0 = __floats2bfloat162_rn(v00, v01);
                __nv_bfloat162 p1 = __floats2bfloat162_rn(v10, v11);
                *(unsigned*)&Cb[(size_t)r0 * N + col] = *(unsigned*)&p0;
                *(unsigned*)&Cb[(size_t)r1 * N + col] = *(unsigned*)&p1;
            } else {
                if (MODE == 2 || MODE == 3) {
                    v00 += res[(size_t)d0 * N + col];
                    v01 += res[(size_t)d0 * N + col + 1];
                    v10 += res[(size_t)d1 * N + col];
                    v11 += res[(size_t)d1 * N + col + 1];
                }
                *(float2*)&Cf[(size_t)d0 * N + col] = make_float2(v00, v01);
                *(float2*)&Cf[(size_t)d1 * N + col] = make_float2(v10, v11);
            }
        }
    }
}

// ---------------------------------------------------------------------------
// Attention: one CTA per (window, head); bf16 output (feeds proj GEMM)
// ---------------------------------------------------------------------------
__global__ void __launch_bounds__(256)
attn_kernel(const float* __restrict__ qkv, const float* __restrict__ relt,
            __nv_bfloat16* __restrict__ outp)
{
    int blk  = blockIdx.x;
    int win  = blk / NHEAD;
    int head = blk % NHEAD;

    __shared__ float q [49][32];
    __shared__ float kk[49][32];
    __shared__ float vv[49][32];
    __shared__ float S [49][56];
    __shared__ int   cnt[49];

    int tid = threadIdx.x;

    for (int idx = tid; idx < 49 * 32; idx += 256) {
        int n = idx >> 5, d = idx & 31;
        size_t base = (size_t)(win * 49 + n) * 1152 + head * 32 + d;
        q [n][d] = qkv[base]       * ATT_SCALE;
        kk[n][d] = qkv[base + 384];
        vv[n][d] = qkv[base + 768];
    }
    if (tid < 49) {
        int wi = win & 63;
        int wh = wi >> 3, ww = wi & 7;
        int i = tid / 7, j = tid % 7;
        int h = wh * 7 + i, w = ww * 7 + j;
        int rh = (h < HH - WSZ)   ? 0 : (h < HH - SHIFT   ? 1 : 2);
        int rw = (w < WWID - WSZ) ? 0 : (w < WWID - SHIFT ? 1 : 2);
        cnt[tid] = rh * 3 + rw;
    }
    __syncthreads();

    for (int p = tid; p < 49 * 49; p += 256) {
        int n = p / 49, m = p % 49;
        float acc = 0.f;
        #pragma unroll
        for (int d = 0; d < 32; d++) acc = fmaf(q[n][d], kk[m][d], acc);
        int di = n / 7 - m / 7 + 6;
        int dj = n % 7 - m % 7 + 6;
        float bias = relt[(di * 13 + dj) * NHEAD + head];
        float mask = (cnt[n] != cnt[m]) ? -100.f : 0.f;
        S[n][m] = acc + bias + mask;
    }
    __syncthreads();

    int wid = tid >> 5, lane = tid & 31;
    for (int n = wid; n < 49; n += 8) {
        float v0 = S[n][lane];
        float v1 = (lane < 17) ? S[n][lane + 32] : -1e30f;
        float mx = fmaxf(v0, v1);
        #pragma unroll
        for (int off = 16; off; off >>= 1)
            mx = fmaxf(mx, __shfl_xor_sync(~0u, mx, off));
        float e0 = expf(v0 - mx);
        float e1 = (lane < 17) ? expf(v1 - mx) : 0.f;
        float sm = e0 + e1;
        #pragma unroll
        for (int off = 16; off; off >>= 1)
            sm += __shfl_xor_sync(~0u, sm, off);
        float inv = 1.f / sm;
        S[n][lane] = e0 * inv;
        if (lane < 17) S[n][lane + 32] = e1 * inv;
    }
    __syncthreads();

    for (int idx = tid; idx < 49 * 32; idx += 256) {
        int n = idx >> 5, d = idx & 31;
        float acc = 0.f;
        #pragma unroll
        for (int m = 0; m < 49; m++) acc = fmaf(S[n][m], vv[m][d], acc);
        outp[(size_t)(win * 49 + n) * 384 + head * 32 + d] = __float2bfloat16(acc);
    }
}

// ---------------------------------------------------------------------------
// Launch
// ---------------------------------------------------------------------------
extern "C" void kernel_launch(void* const* d_in, const int* in_sizes, int n_in,
                              void* d_out, int out_size)
{
    const float* x      = (const float*)d_in[0];
    const float* ln1_g  = (const float*)d_in[1];
    const float* ln1_b  = (const float*)d_in[2];
    const float* ln2_g  = (const float*)d_in[3];
    const float* ln2_b  = (const float*)d_in[4];
    const float* qkv_w  = (const float*)d_in[5];
    const float* qkv_b  = (const float*)d_in[6];
    const float* proj_w = (const float*)d_in[7];
    const float* proj_b = (const float*)d_in[8];
    const float* mlp_w1 = (const float*)d_in[9];
    const float* mlp_b1 = (const float*)d_in[10];
    const float* mlp_w2 = (const float*)d_in[11];
    const float* mlp_b2 = (const float*)d_in[12];
    const float* relt   = (const float*)d_in[13];
    float* out = (float*)d_out;

    __nv_bfloat16 *wins, *att, *ln2o, *hbuf, *wtq, *wtp, *wt1, *wt2;
    float *qkvb, *x1;
    cudaGetSymbolAddress((void**)&wins, g_wins);
    cudaGetSymbolAddress((void**)&qkvb, g_qkv);
    cudaGetSymbolAddress((void**)&att,  g_att);
    cudaGetSymbolAddress((void**)&x1,   g_x1);
    cudaGetSymbolAddress((void**)&ln2o, g_ln2);
    cudaGetSymbolAddress((void**)&hbuf, g_h);
    cudaGetSymbolAddress((void**)&wtq,  g_wt_qkv);
    cudaGetSymbolAddress((void**)&wtp,  g_wt_proj);
    cudaGetSymbolAddress((void**)&wt1,  g_wt_m1);
    cudaGetSymbolAddress((void**)&wt2,  g_wt_m2);

    // 0. weight transpose + bf16 convert
    transpose_w<<<dim3(384 / 32, 1152 / 32), 256>>>(qkv_w,  wtq, 384, 1152);
    transpose_w<<<dim3(384 / 32,  384 / 32), 256>>>(proj_w, wtp, 384, 384);
    transpose_w<<<dim3(384 / 32, 1536 / 32), 256>>>(mlp_w1, wt1, 384, 1536);
    transpose_w<<<dim3(1536 / 32, 384 / 32), 256>>>(mlp_w2, wt2, 1536, 384);

    // 1. LN1 + cyclic shift + window partition -> bf16
    ln_kernel<<<TOK, 384>>>(x, ln1_g, ln1_b, wins, 1);

    // 2. QKV GEMM: [50176,384] @ [384,1152] -> fp32
    gemm_tc<0><<<dim3(9, TOK / 256), 256>>>(
        wins, wtq, qkv_b, nullptr, qkvb, nullptr, TOK, 1152, 384);

    // 3. Windowed attention -> bf16
    attn_kernel<<<NWIN * NHEAD, 256>>>(qkvb, relt, att);

    // 4. Proj GEMM + window reverse + reverse roll + residual -> fp32
    gemm_tc<2><<<dim3(3, TOK / 256), 256>>>(
        att, wtp, proj_b, x, x1, nullptr, TOK, 384, 384);

    // 5. LN2 -> bf16
    ln_kernel<<<TOK, 384>>>(x1, ln2_g, ln2_b, ln2o, 0);

    // 6. MLP1 + GELU: [50176,384] @ [384,1536] -> bf16
    gemm_tc<1><<<dim3(12, TOK / 256), 256>>>(
        ln2o, wt1, mlp_b1, nullptr, nullptr, hbuf, TOK, 1536, 384);

    // 7. MLP2 + residual: [50176,1536] @ [1536,384] -> d_out
    gemm_tc<3><<<dim3(3, TOK / 256), 256>>>(
        hbuf, wt2, mlp_b2, x1, out, nullptr, TOK, 384, 1536);
}

// round 10
// speedup vs baseline: 1.1778x; 1.1778x over previous
#include <cuda_runtime.h>
#include <cuda_bf16.h>
#include <math.h>
#include <stdint.h>

// ---------------------------------------------------------------------------
// Problem constants
// ---------------------------------------------------------------------------
constexpr int BATCH = 16;
constexpr int HH    = 56;
constexpr int WWID  = 56;
constexpr int CDIM  = 384;
constexpr int NHEAD = 12;
constexpr int WSZ   = 7;
constexpr int SHIFT = 3;
constexpr int NTOK  = 49;
constexpr int NWIN  = BATCH * 64;
constexpr int TOK   = NWIN * NTOK;        // 50176
constexpr float ATT_SCALE = 0.17677669529663687f;
constexpr float LN_EPS    = 1e-3f;

// ---------------------------------------------------------------------------
// Scratch (device globals)
// ---------------------------------------------------------------------------
__device__ __nv_bfloat16 g_wins[TOK * CDIM];
__device__ float         g_qkv [TOK * 3 * CDIM];
__device__ __nv_bfloat16 g_att [TOK * CDIM];
__device__ float         g_x1  [TOK * CDIM];
__device__ __nv_bfloat16 g_ln2 [TOK * CDIM];
__device__ __nv_bfloat16 g_h   [TOK * 4 * CDIM];
// transposed bf16 weights [N, K]
__device__ __nv_bfloat16 g_wt_qkv [3 * CDIM * CDIM];
__device__ __nv_bfloat16 g_wt_proj[CDIM * CDIM];
__device__ __nv_bfloat16 g_wt_m1  [4 * CDIM * CDIM];
__device__ __nv_bfloat16 g_wt_m2  [4 * CDIM * CDIM];

// ---------------------------------------------------------------------------
// cp.async helpers
// ---------------------------------------------------------------------------
__device__ __forceinline__ void cp_async16(uint32_t smem, const void* g)
{
    asm volatile("cp.async.cg.shared.global [%0], [%1], 16;"
                 :: "r"(smem), "l"(g));
}
#define CP_COMMIT() asm volatile("cp.async.commit_group;")
#define CP_WAIT(n)  asm volatile("cp.async.wait_group %0;" :: "n"(n))

// ---------------------------------------------------------------------------
// Weight transpose + bf16 convert: W[K,N] fp32 -> WT[N,K] bf16
// ---------------------------------------------------------------------------
__global__ void __launch_bounds__(256)
transpose_w(const float* __restrict__ W, __nv_bfloat16* __restrict__ WT,
            int K, int N)
{
    __shared__ float t[32][33];
    int kb = blockIdx.x * 32, nb = blockIdx.y * 32;
    int x = threadIdx.x & 31, y = threadIdx.x >> 5;   // 32 x 8
    #pragma unroll
    for (int dy = 0; dy < 32; dy += 8)
        t[y + dy][x] = W[(size_t)(kb + y + dy) * N + nb + x];
    __syncthreads();
    #pragma unroll
    for (int dy = 0; dy < 32; dy += 8)
        WT[(size_t)(nb + y + dy) * K + kb + x] = __float2bfloat16(t[x][y + dy]);
}

// ---------------------------------------------------------------------------
// LayerNorm (one block per token), bf16 output.
// gather=1 fuses roll(-3,+3) + window partition.
// ---------------------------------------------------------------------------
__global__ void __launch_bounds__(384)
ln_kernel(const float* __restrict__ X, const float* __restrict__ gam,
          const float* __restrict__ bet, __nv_bfloat16* __restrict__ Y, int gather)
{
    int tok = blockIdx.x;
    int src = tok;
    if (gather) {
        int win = tok / NTOK, n = tok % NTOK;
        int b  = win >> 6, wi = win & 63;
        int wh = wi >> 3,  ww = wi & 7;
        int i  = n / WSZ,  j  = n % WSZ;
        int hs = wh * WSZ + i, ws = ww * WSZ + j;
        int sh = hs + SHIFT; if (sh >= HH)  sh -= HH;
        int sw = ws - SHIFT; if (sw < 0)    sw += WWID;
        src = (b * HH + sh) * WWID + sw;
    }
    int c = threadIdx.x;
    float v = X[(size_t)src * CDIM + c];

    float a = v, b2 = v * v;
    #pragma unroll
    for (int off = 16; off; off >>= 1) {
        a  += __shfl_xor_sync(~0u, a,  off);
        b2 += __shfl_xor_sync(~0u, b2, off);
    }
    __shared__ float s1[12], s2[12];
    __shared__ float mu_s, rs_s;
    int wid = threadIdx.x >> 5, lane = threadIdx.x & 31;
    if (!lane) { s1[wid] = a; s2[wid] = b2; }
    __syncthreads();
    if (threadIdx.x == 0) {
        float sa = 0.f, sb = 0.f;
        #pragma unroll
        for (int k = 0; k < 12; k++) { sa += s1[k]; sb += s2[k]; }
        float mu  = sa / CDIM;
        float var = sb / CDIM - mu * mu;
        mu_s = mu;
        rs_s = rsqrtf(var + LN_EPS);
    }
    __syncthreads();
    Y[(size_t)tok * CDIM + c] =
        __float2bfloat16((v - mu_s) * rs_s * gam[c] + bet[c]);
}

__device__ __forceinline__ int dest_row(int tok)
{
    int win = tok / NTOK, n = tok % NTOK;
    int b  = win >> 6, wi = win & 63;
    int wh = wi >> 3,  ww = wi & 7;
    int i  = n / WSZ,  j  = n % WSZ;
    int hs = wh * WSZ + i, ws = ww * WSZ + j;
    int h = hs + SHIFT; if (h >= HH)   h -= HH;
    int w = ws + SHIFT; if (w >= WWID) w -= WWID;
    return (b * HH + h) * WWID + w;
}

// ---------------------------------------------------------------------------
// bf16 mma.sync GEMM. 128x128 CTA tile, BK=16, 8 warps (64x32 warp tile) —
// round-8 proven geometry — with a 4-stage cp.async.cg producer pipeline
// (L1-bypassing 16B LDGSTS straight into swizzled SMEM).
// A SMEM layout (m 0..127, kp 0..7) — round-8 verified:
//   addr = ((m>>4)*4 + ((m>>3)&1) + 2*(kp>>2))*32 + (((m&7)*4 + (kp&3)) ^ ((kp>>2)<<4))
// B SMEM layout (n 0..127, kp 0..7) — contiguous-per-thread, XOR swizzled:
//   addr = n*8 + (kp ^ (((n>>2)&1)<<2))
// Both store and consume phases conflict-free (bank enumeration verified).
// MODE 0: +bias -> fp32 Cf   MODE 1: +bias,GELU -> bf16 Cb
// MODE 2: +bias,scatter+res -> fp32 Cf   MODE 3: +bias,+res -> fp32 Cf
// Requires M%128==0, N%128==0, K%16==0, K/16 >= 4.
// ---------------------------------------------------------------------------
__device__ __forceinline__ void mma_bf16(float* c, const unsigned* a, const unsigned* b)
{
    asm volatile(
        "mma.sync.aligned.m16n8k16.row.col.f32.bf16.bf16.f32 "
        "{%0,%1,%2,%3}, {%4,%5,%6,%7}, {%8,%9}, {%0,%1,%2,%3};"
        : "+f"(c[0]), "+f"(c[1]), "+f"(c[2]), "+f"(c[3])
        : "r"(a[0]), "r"(a[1]), "r"(a[2]), "r"(a[3]), "r"(b[0]), "r"(b[1]));
}

template<int MODE>
__global__ void __launch_bounds__(256)
gemm_tc(const __nv_bfloat16* __restrict__ A, const __nv_bfloat16* __restrict__ Bt,
        const float* __restrict__ bias, const float* __restrict__ res,
        float* __restrict__ Cf, __nv_bfloat16* __restrict__ Cb,
        int M, int N, int K)
{
    constexpr int STAGES = 4;
    __shared__ __align__(16) unsigned As[STAGES][1024];
    __shared__ __align__(16) unsigned Bs[STAGES][1024];

    const int tid  = threadIdx.x;
    const int bm   = blockIdx.y * 128, bn = blockIdx.x * 128;
    const int warp = tid >> 5, lane = tid & 31;
    const int wm   = warp & 1, wn = warp >> 1;       // 2 x 4 warp grid

    // -------- producer mapping (one 16B cp.async per operand per ktile) ----
    const int ma = tid >> 1, ha = tid & 1;
    const __nv_bfloat16* Ag = A + (size_t)(bm + ma) * K + ha * 8;
    const int aOff = ((ma >> 4) * 4 + ((ma >> 3) & 1) + 2 * ha) * 32
                   + (((ma & 7) * 4) ^ (ha << 4));

    const int nb = tid >> 1, hb = tid & 1;
    const __nv_bfloat16* Bg = Bt + (size_t)(bn + nb) * K + hb * 8;
    const int bOff = nb * 8 + ((hb * 4) ^ (((nb >> 2) & 1) << 2));

    const uint32_t aSm = (uint32_t)__cvta_generic_to_shared(&As[0][0]) + aOff * 4;
    const uint32_t bSm = (uint32_t)__cvta_generic_to_shared(&Bs[0][0]) + bOff * 4;

    float acc[16][4];
    #pragma unroll
    for (int i = 0; i < 16; i++)
        #pragma unroll
        for (int j = 0; j < 4; j++) acc[i][j] = 0.f;

    const int NC = K >> 4;

    // prologue: prefetch STAGES-1 ktiles
    #pragma unroll
    for (int s = 0; s < STAGES - 1; s++) {
        cp_async16(aSm + s * 4096, Ag + s * 16);
        cp_async16(bSm + s * 4096, Bg + s * 16);
        CP_COMMIT();
    }

    for (int c = 0; c < NC; c++) {
        const int st = c & (STAGES - 1);
        CP_WAIT(STAGES - 2);
        __syncthreads();

        unsigned afr[4][4], bfr[4][2];
        #pragma unroll
        for (int i = 0; i < 4; i++) {
            int blk = (wm * 4 + i) * 4;
            afr[i][0] = As[st][(blk + 0) * 32 + lane];
            afr[i][1] = As[st][(blk + 1) * 32 + lane];
            afr[i][2] = As[st][(blk + 2) * 32 + (lane ^ 16)];
            afr[i][3] = As[st][(blk + 3) * 32 + (lane ^ 16)];
        }
        #pragma unroll
        for (int j = 0; j < 4; j++) {
            int n    = wn * 32 + j * 8 + (lane >> 2);
            int flip = ((n >> 2) & 1) << 2;
            bfr[j][0] = Bs[st][n * 8 + ((lane & 3) ^ flip)];
            bfr[j][1] = Bs[st][n * 8 + (((lane & 3) + 4) ^ flip)];
        }
        #pragma unroll
        for (int i = 0; i < 4; i++)
            #pragma unroll
            for (int j = 0; j < 4; j++)
                mma_bf16(acc[i * 4 + j], afr[i], bfr[j]);

        const int nc = c + STAGES - 1;
        if (nc < NC) {
            const int ns = nc & (STAGES - 1);
            cp_async16(aSm + ns * 4096, Ag + (size_t)nc * 16);
            cp_async16(bSm + ns * 4096, Bg + (size_t)nc * 16);
        }
        CP_COMMIT();
    }

    // ---- epilogue ----
    const int g = lane >> 2, t = lane & 3;
    #pragma unroll
    for (int i = 0; i < 4; i++) {
        int r0 = bm + wm * 64 + i * 16 + g;
        int r1 = r0 + 8;
        int d0 = (MODE == 2) ? dest_row(r0) : r0;
        int d1 = (MODE == 2) ? dest_row(r1) : r1;
        #pragma unroll
        for (int j = 0; j < 4; j++) {
            int col = bn + wn * 32 + j * 8 + t * 2;
            float bc0 = bias[col], bc1 = bias[col + 1];
            float v00 = acc[i * 4 + j][0] + bc0;
            float v01 = acc[i * 4 + j][1] + bc1;
            float v10 = acc[i * 4 + j][2] + bc0;
            float v11 = acc[i * 4 + j][3] + bc1;
            if (MODE == 1) {
                v00 = 0.5f * v00 * (1.0f + erff(v00 * 0.70710678118654752f));
                v01 = 0.5f * v01 * (1.0f + erff(v01 * 0.70710678118654752f));
                v10 = 0.5f * v10 * (1.0f + erff(v10 * 0.70710678118654752f));
                v11 = 0.5f * v11 * (1.0f + erff(v11 * 0.70710678118654752f));
                __nv_bfloat162 p0 = __floats2bfloat162_rn(v00, v01);
                __nv_bfloat162 p1 = __floats2bfloat162_rn(v10, v11);
                *(unsigned*)&Cb[(size_t)r0 * N + col] = *(unsigned*)&p0;
                *(unsigned*)&Cb[(size_t)r1 * N + col] = *(unsigned*)&p1;
            } else {
                if (MODE == 2 || MODE == 3) {
                    v00 += res[(size_t)d0 * N + col];
                    v01 += res[(size_t)d0 * N + col + 1];
                    v10 += res[(size_t)d1 * N + col];
                    v11 += res[(size_t)d1 * N + col + 1];
                }
                *(float2*)&Cf[(size_t)d0 * N + col] = make_float2(v00, v01);
                *(float2*)&Cf[(size_t)d1 * N + col] = make_float2(v10, v11);
            }
        }
    }
}

// ---------------------------------------------------------------------------
// Attention: one CTA per (window, head); bf16 output (feeds proj GEMM)
// ---------------------------------------------------------------------------
__global__ void __launch_bounds__(256)
attn_kernel(const float* __restrict__ qkv, const float* __restrict__ relt,
            __nv_bfloat16* __restrict__ outp)
{
    int blk  = blockIdx.x;
    int win  = blk / NHEAD;
    int head = blk % NHEAD;

    __shared__ float q [49][32];
    __shared__ float kk[49][32];
    __shared__ float vv[49][32];
    __shared__ float S [49][56];
    __shared__ int   cnt[49];

    int tid = threadIdx.x;

    for (int idx = tid; idx < 49 * 32; idx += 256) {
        int n = idx >> 5, d = idx & 31;
        size_t base = (size_t)(win * 49 + n) * 1152 + head * 32 + d;
        q [n][d] = qkv[base]       * ATT_SCALE;
        kk[n][d] = qkv[base + 384];
        vv[n][d] = qkv[base + 768];
    }
    if (tid < 49) {
        int wi = win & 63;
        int wh = wi >> 3, ww = wi & 7;
        int i = tid / 7, j = tid % 7;
        int h = wh * 7 + i, w = ww * 7 + j;
        int rh = (h < HH - WSZ)   ? 0 : (h < HH - SHIFT   ? 1 : 2);
        int rw = (w < WWID - WSZ) ? 0 : (w < WWID - SHIFT ? 1 : 2);
        cnt[tid] = rh * 3 + rw;
    }
    __syncthreads();

    for (int p = tid; p < 49 * 49; p += 256) {
        int n = p / 49, m = p % 49;
        float acc = 0.f;
        #pragma unroll
        for (int d = 0; d < 32; d++) acc = fmaf(q[n][d], kk[m][d], acc);
        int di = n / 7 - m / 7 + 6;
        int dj = n % 7 - m % 7 + 6;
        float bias = relt[(di * 13 + dj) * NHEAD + head];
        float mask = (cnt[n] != cnt[m]) ? -100.f : 0.f;
        S[n][m] = acc + bias + mask;
    }
    __syncthreads();

    int wid = tid >> 5, lane = tid & 31;
    for (int n = wid; n < 49; n += 8) {
        float v0 = S[n][lane];
        float v1 = (lane < 17) ? S[n][lane + 32] : -1e30f;
        float mx = fmaxf(v0, v1);
        #pragma unroll
        for (int off = 16; off; off >>= 1)
            mx = fmaxf(mx, __shfl_xor_sync(~0u, mx, off));
        float e0 = expf(v0 - mx);
        float e1 = (lane < 17) ? expf(v1 - mx) : 0.f;
        float sm = e0 + e1;
        #pragma unroll
        for (int off = 16; off; off >>= 1)
            sm += __shfl_xor_sync(~0u, sm, off);
        float inv = 1.f / sm;
        S[n][lane] = e0 * inv;
        if (lane < 17) S[n][lane + 32] = e1 * inv;
    }
    __syncthreads();

    for (int idx = tid; idx < 49 * 32; idx += 256) {
        int n = idx >> 5, d = idx & 31;
        float acc = 0.f;
        #pragma unroll
        for (int m = 0; m < 49; m++) acc = fmaf(S[n][m], vv[m][d], acc);
        outp[(size_t)(win * 49 + n) * 384 + head * 32 + d] = __float2bfloat16(acc);
    }
}

// ---------------------------------------------------------------------------
// Launch
// ---------------------------------------------------------------------------
extern "C" void kernel_launch(void* const* d_in, const int* in_sizes, int n_in,
                              void* d_out, int out_size)
{
    const float* x      = (const float*)d_in[0];
    const float* ln1_g  = (const float*)d_in[1];
    const float* ln1_b  = (const float*)d_in[2];
    const float* ln2_g  = (const float*)d_in[3];
    const float* ln2_b  = (const float*)d_in[4];
    const float* qkv_w  = (const float*)d_in[5];
    const float* qkv_b  = (const float*)d_in[6];
    const float* proj_w = (const float*)d_in[7];
    const float* proj_b = (const float*)d_in[8];
    const float* mlp_w1 = (const float*)d_in[9];
    const float* mlp_b1 = (const float*)d_in[10];
    const float* mlp_w2 = (const float*)d_in[11];
    const float* mlp_b2 = (const float*)d_in[12];
    const float* relt   = (const float*)d_in[13];
    float* out = (float*)d_out;

    __nv_bfloat16 *wins, *att, *ln2o, *hbuf, *wtq, *wtp, *wt1, *wt2;
    float *qkvb, *x1;
    cudaGetSymbolAddress((void**)&wins, g_wins);
    cudaGetSymbolAddress((void**)&qkvb, g_qkv);
    cudaGetSymbolAddress((void**)&att,  g_att);
    cudaGetSymbolAddress((void**)&x1,   g_x1);
    cudaGetSymbolAddress((void**)&ln2o, g_ln2);
    cudaGetSymbolAddress((void**)&hbuf, g_h);
    cudaGetSymbolAddress((void**)&wtq,  g_wt_qkv);
    cudaGetSymbolAddress((void**)&wtp,  g_wt_proj);
    cudaGetSymbolAddress((void**)&wt1,  g_wt_m1);
    cudaGetSymbolAddress((void**)&wt2,  g_wt_m2);

    // 0. weight transpose + bf16 convert
    transpose_w<<<dim3(384 / 32, 1152 / 32), 256>>>(qkv_w,  wtq, 384, 1152);
    transpose_w<<<dim3(384 / 32,  384 / 32), 256>>>(proj_w, wtp, 384, 384);
    transpose_w<<<dim3(384 / 32, 1536 / 32), 256>>>(mlp_w1, wt1, 384, 1536);
    transpose_w<<<dim3(1536 / 32, 384 / 32), 256>>>(mlp_w2, wt2, 1536, 384);

    // 1. LN1 + cyclic shift + window partition -> bf16
    ln_kernel<<<TOK, 384>>>(x, ln1_g, ln1_b, wins, 1);

    // 2. QKV GEMM: [50176,384] @ [384,1152] -> fp32
    gemm_tc<0><<<dim3(9, TOK / 128), 256>>>(
        wins, wtq, qkv_b, nullptr, qkvb, nullptr, TOK, 1152, 384);

    // 3. Windowed attention -> bf16
    attn_kernel<<<NWIN * NHEAD, 256>>>(qkvb, relt, att);

    // 4. Proj GEMM + window reverse + reverse roll + residual -> fp32
    gemm_tc<2><<<dim3(3, TOK / 128), 256>>>(
        att, wtp, proj_b, x, x1, nullptr, TOK, 384, 384);

    // 5. LN2 -> bf16
    ln_kernel<<<TOK, 384>>>(x1, ln2_g, ln2_b, ln2o, 0);

    // 6. MLP1 + GELU: [50176,384] @ [384,1536] -> bf16
    gemm_tc<1><<<dim3(12, TOK / 128), 256>>>(
        ln2o, wt1, mlp_b1, nullptr, nullptr, hbuf, TOK, 1536, 384);

    // 7. MLP2 + residual: [50176,1536] @ [1536,384] -> d_out
    gemm_tc<3><<<dim3(3, TOK / 128), 256>>>(
        hbuf, wt2, mlp_b2, x1, out, nullptr, TOK, 384, 1536);
}

// round 11
// speedup vs baseline: 1.2410x; 1.0536x over previous
#include <cuda_runtime.h>
#include <cuda_bf16.h>
#include <math.h>
#include <stdint.h>

// ---------------------------------------------------------------------------
// Problem constants
// ---------------------------------------------------------------------------
constexpr int BATCH = 16;
constexpr int HH    = 56;
constexpr int WWID  = 56;
constexpr int CDIM  = 384;
constexpr int NHEAD = 12;
constexpr int WSZ   = 7;
constexpr int SHIFT = 3;
constexpr int NTOK  = 49;
constexpr int NWIN  = BATCH * 64;
constexpr int TOK   = NWIN * NTOK;        // 50176
constexpr float ATT_SCALE = 0.17677669529663687f;
constexpr float LN_EPS    = 1e-3f;

// ---------------------------------------------------------------------------
// Scratch (device globals)
// ---------------------------------------------------------------------------
__device__ __nv_bfloat16 g_wins[TOK * CDIM];
__device__ float         g_qkv [TOK * 3 * CDIM];
__device__ __nv_bfloat16 g_att [TOK * CDIM];
__device__ float         g_x1  [TOK * CDIM];
__device__ __nv_bfloat16 g_ln2 [TOK * CDIM];
__device__ __nv_bfloat16 g_h   [TOK * 4 * CDIM];
// transposed bf16 weights [N, K]
__device__ __nv_bfloat16 g_wt_qkv [3 * CDIM * CDIM];
__device__ __nv_bfloat16 g_wt_proj[CDIM * CDIM];
__device__ __nv_bfloat16 g_wt_m1  [4 * CDIM * CDIM];
__device__ __nv_bfloat16 g_wt_m2  [4 * CDIM * CDIM];

// ---------------------------------------------------------------------------
// cp.async helpers
// ---------------------------------------------------------------------------
__device__ __forceinline__ void cp_async16(uint32_t smem, const void* g)
{
    asm volatile("cp.async.cg.shared.global [%0], [%1], 16;"
                 :: "r"(smem), "l"(g));
}
#define CP_COMMIT() asm volatile("cp.async.commit_group;")
#define CP_WAIT(n)  asm volatile("cp.async.wait_group %0;" :: "n"(n))

// ---------------------------------------------------------------------------
// Weight transpose + bf16 convert: W[K,N] fp32 -> WT[N,K] bf16
// ---------------------------------------------------------------------------
__global__ void __launch_bounds__(256)
transpose_w(const float* __restrict__ W, __nv_bfloat16* __restrict__ WT,
            int K, int N)
{
    __shared__ float t[32][33];
    int kb = blockIdx.x * 32, nb = blockIdx.y * 32;
    int x = threadIdx.x & 31, y = threadIdx.x >> 5;   // 32 x 8
    #pragma unroll
    for (int dy = 0; dy < 32; dy += 8)
        t[y + dy][x] = W[(size_t)(kb + y + dy) * N + nb + x];
    __syncthreads();
    #pragma unroll
    for (int dy = 0; dy < 32; dy += 8)
        WT[(size_t)(nb + y + dy) * K + kb + x] = __float2bfloat16(t[x][y + dy]);
}

// ---------------------------------------------------------------------------
// LayerNorm: one WARP per token, 8 tokens per 256-thread block. No block
// barriers; 12 channels/lane via 3 float4 loads; shuffle reduction.
// gather=1 fuses roll(-3,+3) + window partition. bf16 output.
// ---------------------------------------------------------------------------
__global__ void __launch_bounds__(256)
ln_kernel(const float* __restrict__ X, const float* __restrict__ gam,
          const float* __restrict__ bet, __nv_bfloat16* __restrict__ Y, int gather)
{
    const int warp = threadIdx.x >> 5, lane = threadIdx.x & 31;
    const int tok = blockIdx.x * 8 + warp;
    int src = tok;
    if (gather) {
        int win = tok / NTOK, n = tok % NTOK;
        int b  = win >> 6, wi = win & 63;
        int wh = wi >> 3,  ww = wi & 7;
        int i  = n / WSZ,  j  = n % WSZ;
        int hs = wh * WSZ + i, ws = ww * WSZ + j;
        int sh = hs + SHIFT; if (sh >= HH)  sh -= HH;
        int sw = ws - SHIFT; if (sw < 0)    sw += WWID;
        src = (b * HH + sh) * WWID + sw;
    }
    const float4* xp = (const float4*)(X + (size_t)src * CDIM);
    float4 v0 = xp[lane], v1 = xp[lane + 32], v2 = xp[lane + 64];

    float s  = v0.x + v0.y + v0.z + v0.w
             + v1.x + v1.y + v1.z + v1.w
             + v2.x + v2.y + v2.z + v2.w;
    float s2 = v0.x * v0.x + v0.y * v0.y + v0.z * v0.z + v0.w * v0.w
             + v1.x * v1.x + v1.y * v1.y + v1.z * v1.z + v1.w * v1.w
             + v2.x * v2.x + v2.y * v2.y + v2.z * v2.z + v2.w * v2.w;
    #pragma unroll
    for (int off = 16; off; off >>= 1) {
        s  += __shfl_xor_sync(~0u, s,  off);
        s2 += __shfl_xor_sync(~0u, s2, off);
    }
    const float mu = s * (1.0f / CDIM);
    const float rs = rsqrtf(s2 * (1.0f / CDIM) - mu * mu + LN_EPS);

    const float4* gp = (const float4*)gam;
    const float4* bp = (const float4*)bet;
    uint2* yp = (uint2*)(Y + (size_t)tok * CDIM);

    #pragma unroll
    for (int q = 0; q < 3; q++) {
        float4 v = (q == 0) ? v0 : (q == 1) ? v1 : v2;
        float4 gg = gp[lane + q * 32];
        float4 bb = bp[lane + q * 32];
        float o0 = (v.x - mu) * rs * gg.x + bb.x;
        float o1 = (v.y - mu) * rs * gg.y + bb.y;
        float o2 = (v.z - mu) * rs * gg.z + bb.z;
        float o3 = (v.w - mu) * rs * gg.w + bb.w;
        __nv_bfloat162 p0 = __floats2bfloat162_rn(o0, o1);
        __nv_bfloat162 p1 = __floats2bfloat162_rn(o2, o3);
        yp[lane + q * 32] = make_uint2(*(unsigned*)&p0, *(unsigned*)&p1);
    }
}

__device__ __forceinline__ int dest_row(int tok)
{
    int win = tok / NTOK, n = tok % NTOK;
    int b  = win >> 6, wi = win & 63;
    int wh = wi >> 3,  ww = wi & 7;
    int i  = n / WSZ,  j  = n % WSZ;
    int hs = wh * WSZ + i, ws = ww * WSZ + j;
    int h = hs + SHIFT; if (h >= HH)   h -= HH;
    int w = ws + SHIFT; if (w >= WWID) w -= WWID;
    return (b * HH + h) * WWID + w;
}

// ---------------------------------------------------------------------------
// bf16 mma.sync GEMM. 128x128 CTA tile, 8 warps (64x32 warp tile), 4-stage
// cp.async.cg pipeline with BK=32 per stage (two verified 16-k sub-tiles)
// — halves barrier/commit count vs BK=16.
// A sub-tile layout (m, kp):  ((m>>4)*4 + ((m>>3)&1) + 2*(kp>>2))*32
//                             + (((m&7)*4 + (kp&3)) ^ ((kp>>2)<<4))
// B sub-tile layout (n, kp):  n*8 + (kp ^ (((n>>2)&1)<<2))
// MODE 0: +bias -> fp32 Cf   MODE 1: +bias,GELU -> bf16 Cb
// MODE 2: +bias,scatter+res -> fp32 Cf   MODE 3: +bias,+res -> fp32 Cf
// Requires M%128==0, N%128==0, K%32==0, K/32 >= 4.
// ---------------------------------------------------------------------------
__device__ __forceinline__ void mma_bf16(float* c, const unsigned* a, const unsigned* b)
{
    asm volatile(
        "mma.sync.aligned.m16n8k16.row.col.f32.bf16.bf16.f32 "
        "{%0,%1,%2,%3}, {%4,%5,%6,%7}, {%8,%9}, {%0,%1,%2,%3};"
        : "+f"(c[0]), "+f"(c[1]), "+f"(c[2]), "+f"(c[3])
        : "r"(a[0]), "r"(a[1]), "r"(a[2]), "r"(a[3]), "r"(b[0]), "r"(b[1]));
}

template<int MODE>
__global__ void __launch_bounds__(256)
gemm_tc(const __nv_bfloat16* __restrict__ A, const __nv_bfloat16* __restrict__ Bt,
        const float* __restrict__ bias, const float* __restrict__ res,
        float* __restrict__ Cf, __nv_bfloat16* __restrict__ Cb,
        int M, int N, int K)
{
    constexpr int STAGES = 4;
    __shared__ __align__(16) unsigned As[STAGES][2048];   // 8KB/stage (BK=32)
    __shared__ __align__(16) unsigned Bs[STAGES][2048];

    const int tid  = threadIdx.x;
    const int bm   = blockIdx.y * 128, bn = blockIdx.x * 128;
    const int warp = tid >> 5, lane = tid & 31;
    const int wm   = warp & 1, wn = warp >> 1;       // 2 x 4 warp grid

    // -------- producer mapping (two 16B cp.async per operand per stage) ----
    const int ma = tid >> 1, ha = tid & 1;
    const __nv_bfloat16* Ag = A + (size_t)(bm + ma) * K + ha * 8;
    const int aOff = ((ma >> 4) * 4 + ((ma >> 3) & 1) + 2 * ha) * 32
                   + (((ma & 7) * 4) ^ (ha << 4));

    const int nb = tid >> 1, hb = tid & 1;
    const __nv_bfloat16* Bg = Bt + (size_t)(bn + nb) * K + hb * 8;
    const int bOff = nb * 8 + ((hb * 4) ^ (((nb >> 2) & 1) << 2));

    const uint32_t aSm = (uint32_t)__cvta_generic_to_shared(&As[0][0]) + aOff * 4;
    const uint32_t bSm = (uint32_t)__cvta_generic_to_shared(&Bs[0][0]) + bOff * 4;

    float acc[16][4];
    #pragma unroll
    for (int i = 0; i < 16; i++)
        #pragma unroll
        for (int j = 0; j < 4; j++) acc[i][j] = 0.f;

    const int NC = K >> 5;                 // 32-k stages

    // prologue: prefetch STAGES-1 stages
    #pragma unroll
    for (int s = 0; s < STAGES - 1; s++) {
        cp_async16(aSm + s * 8192,        Ag + s * 32);
        cp_async16(aSm + s * 8192 + 4096, Ag + s * 32 + 16);
        cp_async16(bSm + s * 8192,        Bg + s * 32);
        cp_async16(bSm + s * 8192 + 4096, Bg + s * 32 + 16);
        CP_COMMIT();
    }

    for (int c = 0; c < NC; c++) {
        const int st = c & (STAGES - 1);
        CP_WAIT(STAGES - 2);
        __syncthreads();

        #pragma unroll
        for (int sub = 0; sub < 2; sub++) {
            const unsigned* Asb = &As[st][sub * 1024];
            const unsigned* Bsb = &Bs[st][sub * 1024];
            unsigned afr[4][4], bfr[4][2];
            #pragma unroll
            for (int i = 0; i < 4; i++) {
                int blk = (wm * 4 + i) * 4;
                afr[i][0] = Asb[(blk + 0) * 32 + lane];
                afr[i][1] = Asb[(blk + 1) * 32 + lane];
                afr[i][2] = Asb[(blk + 2) * 32 + (lane ^ 16)];
                afr[i][3] = Asb[(blk + 3) * 32 + (lane ^ 16)];
            }
            #pragma unroll
            for (int j = 0; j < 4; j++) {
                int n    = wn * 32 + j * 8 + (lane >> 2);
                int flip = ((n >> 2) & 1) << 2;
                bfr[j][0] = Bsb[n * 8 + ((lane & 3) ^ flip)];
                bfr[j][1] = Bsb[n * 8 + (((lane & 3) + 4) ^ flip)];
            }
            #pragma unroll
            for (int i = 0; i < 4; i++)
                #pragma unroll
                for (int j = 0; j < 4; j++)
                    mma_bf16(acc[i * 4 + j], afr[i], bfr[j]);
        }

        const int nc = c + STAGES - 1;
        if (nc < NC) {
            const int ns = nc & (STAGES - 1);
            cp_async16(aSm + ns * 8192,        Ag + (size_t)nc * 32);
            cp_async16(aSm + ns * 8192 + 4096, Ag + (size_t)nc * 32 + 16);
            cp_async16(bSm + ns * 8192,        Bg + (size_t)nc * 32);
            cp_async16(bSm + ns * 8192 + 4096, Bg + (size_t)nc * 32 + 16);
        }
        CP_COMMIT();
    }

    // ---- epilogue ----
    const int g = lane >> 2, t = lane & 3;
    #pragma unroll
    for (int i = 0; i < 4; i++) {
        int r0 = bm + wm * 64 + i * 16 + g;
        int r1 = r0 + 8;
        int d0 = (MODE == 2) ? dest_row(r0) : r0;
        int d1 = (MODE == 2) ? dest_row(r1) : r1;
        #pragma unroll
        for (int j = 0; j < 4; j++) {
            int col = bn + wn * 32 + j * 8 + t * 2;
            float bc0 = bias[col], bc1 = bias[col + 1];
            float v00 = acc[i * 4 + j][0] + bc0;
            float v01 = acc[i * 4 + j][1] + bc1;
            float v10 = acc[i * 4 + j][2] + bc0;
            float v11 = acc[i * 4 + j][3] + bc1;
            if (MODE == 1) {
                v00 = 0.5f * v00 * (1.0f + erff(v00 * 0.70710678118654752f));
                v01 = 0.5f * v01 * (1.0f + erff(v01 * 0.70710678118654752f));
                v10 = 0.5f * v10 * (1.0f + erff(v10 * 0.70710678118654752f));
                v11 = 0.5f * v11 * (1.0f + erff(v11 * 0.70710678118654752f));
                __nv_bfloat162 p0 = __floats2bfloat162_rn(v00, v01);
                __nv_bfloat162 p1 = __floats2bfloat162_rn(v10, v11);
                *(unsigned*)&Cb[(size_t)r0 * N + col] = *(unsigned*)&p0;
                *(unsigned*)&Cb[(size_t)r1 * N + col] = *(unsigned*)&p1;
            } else {
                if (MODE == 2 || MODE == 3) {
                    v00 += res[(size_t)d0 * N + col];
                    v01 += res[(size_t)d0 * N + col + 1];
                    v10 += res[(size_t)d1 * N + col];
                    v11 += res[(size_t)d1 * N + col + 1];
                }
                *(float2*)&Cf[(size_t)d0 * N + col] = make_float2(v00, v01);
                *(float2*)&Cf[(size_t)d1 * N + col] = make_float2(v10, v11);
            }
        }
    }
}

// ---------------------------------------------------------------------------
// Attention: one CTA per (window, head); bf16 output (feeds proj GEMM)
// ---------------------------------------------------------------------------
__global__ void __launch_bounds__(256)
attn_kernel(const float* __restrict__ qkv, const float* __restrict__ relt,
            __nv_bfloat16* __restrict__ outp)
{
    int blk  = blockIdx.x;
    int win  = blk / NHEAD;
    int head = blk % NHEAD;

    __shared__ float q [49][32];
    __shared__ float kk[49][32];
    __shared__ float vv[49][32];
    __shared__ float S [49][56];
    __shared__ int   cnt[49];

    int tid = threadIdx.x;

    for (int idx = tid; idx < 49 * 32; idx += 256) {
        int n = idx >> 5, d = idx & 31;
        size_t base = (size_t)(win * 49 + n) * 1152 + head * 32 + d;
        q [n][d] = qkv[base]       * ATT_SCALE;
        kk[n][d] = qkv[base + 384];
        vv[n][d] = qkv[base + 768];
    }
    if (tid < 49) {
        int wi = win & 63;
        int wh = wi >> 3, ww = wi & 7;
        int i = tid / 7, j = tid % 7;
        int h = wh * 7 + i, w = ww * 7 + j;
        int rh = (h < HH - WSZ)   ? 0 : (h < HH - SHIFT   ? 1 : 2);
        int rw = (w < WWID - WSZ) ? 0 : (w < WWID - SHIFT ? 1 : 2);
        cnt[tid] = rh * 3 + rw;
    }
    __syncthreads();

    for (int p = tid; p < 49 * 49; p += 256) {
        int n = p / 49, m = p % 49;
        float acc = 0.f;
        #pragma unroll
        for (int d = 0; d < 32; d++) acc = fmaf(q[n][d], kk[m][d], acc);
        int di = n / 7 - m / 7 + 6;
        int dj = n % 7 - m % 7 + 6;
        float bias = relt[(di * 13 + dj) * NHEAD + head];
        float mask = (cnt[n] != cnt[m]) ? -100.f : 0.f;
        S[n][m] = acc + bias + mask;
    }
    __syncthreads();

    int wid = tid >> 5, lane = tid & 31;
    for (int n = wid; n < 49; n += 8) {
        float v0 = S[n][lane];
        float v1 = (lane < 17) ? S[n][lane + 32] : -1e30f;
        float mx = fmaxf(v0, v1);
        #pragma unroll
        for (int off = 16; off; off >>= 1)
            mx = fmaxf(mx, __shfl_xor_sync(~0u, mx, off));
        float e0 = expf(v0 - mx);
        float e1 = (lane < 17) ? expf(v1 - mx) : 0.f;
        float sm = e0 + e1;
        #pragma unroll
        for (int off = 16; off; off >>= 1)
            sm += __shfl_xor_sync(~0u, sm, off);
        float inv = 1.f / sm;
        S[n][lane] = e0 * inv;
        if (lane < 17) S[n][lane + 32] = e1 * inv;
    }
    __syncthreads();

    for (int idx = tid; idx < 49 * 32; idx += 256) {
        int n = idx >> 5, d = idx & 31;
        float acc = 0.f;
        #pragma unroll
        for (int m = 0; m < 49; m++) acc = fmaf(S[n][m], vv[m][d], acc);
        outp[(size_t)(win * 49 + n) * 384 + head * 32 + d] = __float2bfloat16(acc);
    }
}

// ---------------------------------------------------------------------------
// Launch
// ---------------------------------------------------------------------------
extern "C" void kernel_launch(void* const* d_in, const int* in_sizes, int n_in,
                              void* d_out, int out_size)
{
    const float* x      = (const float*)d_in[0];
    const float* ln1_g  = (const float*)d_in[1];
    const float* ln1_b  = (const float*)d_in[2];
    const float* ln2_g  = (const float*)d_in[3];
    const float* ln2_b  = (const float*)d_in[4];
    const float* qkv_w  = (const float*)d_in[5];
    const float* qkv_b  = (const float*)d_in[6];
    const float* proj_w = (const float*)d_in[7];
    const float* proj_b = (const float*)d_in[8];
    const float* mlp_w1 = (const float*)d_in[9];
    const float* mlp_b1 = (const float*)d_in[10];
    const float* mlp_w2 = (const float*)d_in[11];
    const float* mlp_b2 = (const float*)d_in[12];
    const float* relt   = (const float*)d_in[13];
    float* out = (float*)d_out;

    __nv_bfloat16 *wins, *att, *ln2o, *hbuf, *wtq, *wtp, *wt1, *wt2;
    float *qkvb, *x1;
    cudaGetSymbolAddress((void**)&wins, g_wins);
    cudaGetSymbolAddress((void**)&qkvb, g_qkv);
    cudaGetSymbolAddress((void**)&att,  g_att);
    cudaGetSymbolAddress((void**)&x1,   g_x1);
    cudaGetSymbolAddress((void**)&ln2o, g_ln2);
    cudaGetSymbolAddress((void**)&hbuf, g_h);
    cudaGetSymbolAddress((void**)&wtq,  g_wt_qkv);
    cudaGetSymbolAddress((void**)&wtp,  g_wt_proj);
    cudaGetSymbolAddress((void**)&wt1,  g_wt_m1);
    cudaGetSymbolAddress((void**)&wt2,  g_wt_m2);

    // 0. weight transpose + bf16 convert
    transpose_w<<<dim3(384 / 32, 1152 / 32), 256>>>(qkv_w,  wtq, 384, 1152);
    transpose_w<<<dim3(384 / 32,  384 / 32), 256>>>(proj_w, wtp, 384, 384);
    transpose_w<<<dim3(384 / 32, 1536 / 32), 256>>>(mlp_w1, wt1, 384, 1536);
    transpose_w<<<dim3(1536 / 32, 384 / 32), 256>>>(mlp_w2, wt2, 1536, 384);

    // 1. LN1 + cyclic shift + window partition -> bf16
    ln_kernel<<<TOK / 8, 256>>>(x, ln1_g, ln1_b, wins, 1);

    // 2. QKV GEMM: [50176,384] @ [384,1152] -> fp32
    gemm_tc<0><<<dim3(9, TOK / 128), 256>>>(
        wins, wtq, qkv_b, nullptr, qkvb, nullptr, TOK, 1152, 384);

    // 3. Windowed attention -> bf16
    attn_kernel<<<NWIN * NHEAD, 256>>>(qkvb, relt, att);

    // 4. Proj GEMM + window reverse + reverse roll + residual -> fp32
    gemm_tc<2><<<dim3(3, TOK / 128), 256>>>(
        att, wtp, proj_b, x, x1, nullptr, TOK, 384, 384);

    // 5. LN2 -> bf16
    ln_kernel<<<TOK / 8, 256>>>(x1, ln2_g, ln2_b, ln2o, 0);

    // 6. MLP1 + GELU: [50176,384] @ [384,1536] -> bf16
    gemm_tc<1><<<dim3(12, TOK / 128), 256>>>(
        ln2o, wt1, mlp_b1, nullptr, nullptr, hbuf, TOK, 1536, 384);

    // 7. MLP2 + residual: [50176,1536] @ [1536,384] -> d_out
    gemm_tc<3><<<dim3(3, TOK / 128), 256>>>(
        hbuf, wt2, mlp_b2, x1, out, nullptr, TOK, 384, 1536);
}

// round 12
// speedup vs baseline: 1.8998x; 1.5308x over previous
#include <cuda_runtime.h>
#include <cuda_bf16.h>
#include <math.h>
#include <stdint.h>

// ---------------------------------------------------------------------------
// Problem constants
// ---------------------------------------------------------------------------
constexpr int BATCH = 16;
constexpr int HH    = 56;
constexpr int WWID  = 56;
constexpr int CDIM  = 384;
constexpr int NHEAD = 12;
constexpr int WSZ   = 7;
constexpr int SHIFT = 3;
constexpr int NTOK  = 49;
constexpr int NWIN  = BATCH * 64;
constexpr int TOK   = NWIN * NTOK;        // 50176
constexpr float ATT_SCALE = 0.17677669529663687f;
constexpr float LN_EPS    = 1e-3f;

// ---------------------------------------------------------------------------
// Scratch (device globals)
// ---------------------------------------------------------------------------
__device__ __nv_bfloat16 g_wins[TOK * CDIM];
__device__ __nv_bfloat16 g_qkv [TOK * 3 * CDIM];     // bf16 now
__device__ __nv_bfloat16 g_att [TOK * CDIM];
__device__ float         g_x1  [TOK * CDIM];
__device__ __nv_bfloat16 g_ln2 [TOK * CDIM];
__device__ __nv_bfloat16 g_h   [TOK * 4 * CDIM];
// transposed bf16 weights [N, K]
__device__ __nv_bfloat16 g_wt_qkv [3 * CDIM * CDIM];
__device__ __nv_bfloat16 g_wt_proj[CDIM * CDIM];
__device__ __nv_bfloat16 g_wt_m1  [4 * CDIM * CDIM];
__device__ __nv_bfloat16 g_wt_m2  [4 * CDIM * CDIM];

// ---------------------------------------------------------------------------
// cp.async helpers
// ---------------------------------------------------------------------------
__device__ __forceinline__ void cp_async16(uint32_t smem, const void* g)
{
    asm volatile("cp.async.cg.shared.global [%0], [%1], 16;"
                 :: "r"(smem), "l"(g));
}
#define CP_COMMIT() asm volatile("cp.async.commit_group;")
#define CP_WAIT(n)  asm volatile("cp.async.wait_group %0;" :: "n"(n))

// ---------------------------------------------------------------------------
// Weight transpose + bf16 convert: W[K,N] fp32 -> WT[N,K] bf16
// ---------------------------------------------------------------------------
__global__ void __launch_bounds__(256)
transpose_w(const float* __restrict__ W, __nv_bfloat16* __restrict__ WT,
            int K, int N)
{
    __shared__ float t[32][33];
    int kb = blockIdx.x * 32, nb = blockIdx.y * 32;
    int x = threadIdx.x & 31, y = threadIdx.x >> 5;   // 32 x 8
    #pragma unroll
    for (int dy = 0; dy < 32; dy += 8)
        t[y + dy][x] = W[(size_t)(kb + y + dy) * N + nb + x];
    __syncthreads();
    #pragma unroll
    for (int dy = 0; dy < 32; dy += 8)
        WT[(size_t)(nb + y + dy) * K + kb + x] = __float2bfloat16(t[x][y + dy]);
}

// ---------------------------------------------------------------------------
// LayerNorm: one WARP per token, 8 tokens per 256-thread block.
// gather=1 fuses roll(-3,+3) + window partition. bf16 output.
// ---------------------------------------------------------------------------
__global__ void __launch_bounds__(256)
ln_kernel(const float* __restrict__ X, const float* __restrict__ gam,
          const float* __restrict__ bet, __nv_bfloat16* __restrict__ Y, int gather)
{
    const int warp = threadIdx.x >> 5, lane = threadIdx.x & 31;
    const int tok = blockIdx.x * 8 + warp;
    int src = tok;
    if (gather) {
        int win = tok / NTOK, n = tok % NTOK;
        int b  = win >> 6, wi = win & 63;
        int wh = wi >> 3,  ww = wi & 7;
        int i  = n / WSZ,  j  = n % WSZ;
        int hs = wh * WSZ + i, ws = ww * WSZ + j;
        int sh = hs + SHIFT; if (sh >= HH)  sh -= HH;
        int sw = ws - SHIFT; if (sw < 0)    sw += WWID;
        src = (b * HH + sh) * WWID + sw;
    }
    const float4* xp = (const float4*)(X + (size_t)src * CDIM);
    float4 v0 = xp[lane], v1 = xp[lane + 32], v2 = xp[lane + 64];

    float s  = v0.x + v0.y + v0.z + v0.w
             + v1.x + v1.y + v1.z + v1.w
             + v2.x + v2.y + v2.z + v2.w;
    float s2 = v0.x * v0.x + v0.y * v0.y + v0.z * v0.z + v0.w * v0.w
             + v1.x * v1.x + v1.y * v1.y + v1.z * v1.z + v1.w * v1.w
             + v2.x * v2.x + v2.y * v2.y + v2.z * v2.z + v2.w * v2.w;
    #pragma unroll
    for (int off = 16; off; off >>= 1) {
        s  += __shfl_xor_sync(~0u, s,  off);
        s2 += __shfl_xor_sync(~0u, s2, off);
    }
    const float mu = s * (1.0f / CDIM);
    const float rs = rsqrtf(s2 * (1.0f / CDIM) - mu * mu + LN_EPS);

    const float4* gp = (const float4*)gam;
    const float4* bp = (const float4*)bet;
    uint2* yp = (uint2*)(Y + (size_t)tok * CDIM);

    #pragma unroll
    for (int q = 0; q < 3; q++) {
        float4 v = (q == 0) ? v0 : (q == 1) ? v1 : v2;
        float4 gg = gp[lane + q * 32];
        float4 bb = bp[lane + q * 32];
        float o0 = (v.x - mu) * rs * gg.x + bb.x;
        float o1 = (v.y - mu) * rs * gg.y + bb.y;
        float o2 = (v.z - mu) * rs * gg.z + bb.z;
        float o3 = (v.w - mu) * rs * gg.w + bb.w;
        __nv_bfloat162 p0 = __floats2bfloat162_rn(o0, o1);
        __nv_bfloat162 p1 = __floats2bfloat162_rn(o2, o3);
        yp[lane + q * 32] = make_uint2(*(unsigned*)&p0, *(unsigned*)&p1);
    }
}

__device__ __forceinline__ int dest_row(int tok)
{
    int win = tok / NTOK, n = tok % NTOK;
    int b  = win >> 6, wi = win & 63;
    int wh = wi >> 3,  ww = wi & 7;
    int i  = n / WSZ,  j  = n % WSZ;
    int hs = wh * WSZ + i, ws = ww * WSZ + j;
    int h = hs + SHIFT; if (h >= HH)   h -= HH;
    int w = ws + SHIFT; if (w >= WWID) w -= WWID;
    return (b * HH + h) * WWID + w;
}

// ---------------------------------------------------------------------------
// bf16 mma.sync GEMM. 128x128 CTA tile, 8 warps (64x32), 4-stage cp.async
// pipeline, BK=32/stage — round-11 proven backbone.
// MODE 0: +bias -> bf16 Cb          MODE 1: +bias,GELU -> bf16 Cb
// MODE 2: +bias,scatter+res -> fp32 Cf   MODE 3: +bias,+res -> fp32 Cf
// Requires M%128==0, N%128==0, K%32==0, K/32 >= 4.
// ---------------------------------------------------------------------------
__device__ __forceinline__ void mma_bf16(float* c, const unsigned* a, const unsigned* b)
{
    asm volatile(
        "mma.sync.aligned.m16n8k16.row.col.f32.bf16.bf16.f32 "
        "{%0,%1,%2,%3}, {%4,%5,%6,%7}, {%8,%9}, {%0,%1,%2,%3};"
        : "+f"(c[0]), "+f"(c[1]), "+f"(c[2]), "+f"(c[3])
        : "r"(a[0]), "r"(a[1]), "r"(a[2]), "r"(a[3]), "r"(b[0]), "r"(b[1]));
}

template<int MODE>
__global__ void __launch_bounds__(256)
gemm_tc(const __nv_bfloat16* __restrict__ A, const __nv_bfloat16* __restrict__ Bt,
        const float* __restrict__ bias, const float* __restrict__ res,
        float* __restrict__ Cf, __nv_bfloat16* __restrict__ Cb,
        int M, int N, int K)
{
    constexpr int STAGES = 4;
    __shared__ __align__(16) unsigned As[STAGES][2048];
    __shared__ __align__(16) unsigned Bs[STAGES][2048];

    const int tid  = threadIdx.x;
    const int bm   = blockIdx.y * 128, bn = blockIdx.x * 128;
    const int warp = tid >> 5, lane = tid & 31;
    const int wm   = warp & 1, wn = warp >> 1;       // 2 x 4 warp grid

    const int ma = tid >> 1, ha = tid & 1;
    const __nv_bfloat16* Ag = A + (size_t)(bm + ma) * K + ha * 8;
    const int aOff = ((ma >> 4) * 4 + ((ma >> 3) & 1) + 2 * ha) * 32
                   + (((ma & 7) * 4) ^ (ha << 4));

    const int nb = tid >> 1, hb = tid & 1;
    const __nv_bfloat16* Bg = Bt + (size_t)(bn + nb) * K + hb * 8;
    const int bOff = nb * 8 + ((hb * 4) ^ (((nb >> 2) & 1) << 2));

    const uint32_t aSm = (uint32_t)__cvta_generic_to_shared(&As[0][0]) + aOff * 4;
    const uint32_t bSm = (uint32_t)__cvta_generic_to_shared(&Bs[0][0]) + bOff * 4;

    float acc[16][4];
    #pragma unroll
    for (int i = 0; i < 16; i++)
        #pragma unroll
        for (int j = 0; j < 4; j++) acc[i][j] = 0.f;

    const int NC = K >> 5;

    #pragma unroll
    for (int s = 0; s < STAGES - 1; s++) {
        cp_async16(aSm + s * 8192,        Ag + s * 32);
        cp_async16(aSm + s * 8192 + 4096, Ag + s * 32 + 16);
        cp_async16(bSm + s * 8192,        Bg + s * 32);
        cp_async16(bSm + s * 8192 + 4096, Bg + s * 32 + 16);
        CP_COMMIT();
    }

    for (int c = 0; c < NC; c++) {
        const int st = c & (STAGES - 1);
        CP_WAIT(STAGES - 2);
        __syncthreads();

        #pragma unroll
        for (int sub = 0; sub < 2; sub++) {
            const unsigned* Asb = &As[st][sub * 1024];
            const unsigned* Bsb = &Bs[st][sub * 1024];
            unsigned afr[4][4], bfr[4][2];
            #pragma unroll
            for (int i = 0; i < 4; i++) {
                int blk = (wm * 4 + i) * 4;
                afr[i][0] = Asb[(blk + 0) * 32 + lane];
                afr[i][1] = Asb[(blk + 1) * 32 + lane];
                afr[i][2] = Asb[(blk + 2) * 32 + (lane ^ 16)];
                afr[i][3] = Asb[(blk + 3) * 32 + (lane ^ 16)];
            }
            #pragma unroll
            for (int j = 0; j < 4; j++) {
                int n    = wn * 32 + j * 8 + (lane >> 2);
                int flip = ((n >> 2) & 1) << 2;
                bfr[j][0] = Bsb[n * 8 + ((lane & 3) ^ flip)];
                bfr[j][1] = Bsb[n * 8 + (((lane & 3) + 4) ^ flip)];
            }
            #pragma unroll
            for (int i = 0; i < 4; i++)
                #pragma unroll
                for (int j = 0; j < 4; j++)
                    mma_bf16(acc[i * 4 + j], afr[i], bfr[j]);
        }

        const int nc = c + STAGES - 1;
        if (nc < NC) {
            const int ns = nc & (STAGES - 1);
            cp_async16(aSm + ns * 8192,        Ag + (size_t)nc * 32);
            cp_async16(aSm + ns * 8192 + 4096, Ag + (size_t)nc * 32 + 16);
            cp_async16(bSm + ns * 8192,        Bg + (size_t)nc * 32);
            cp_async16(bSm + ns * 8192 + 4096, Bg + (size_t)nc * 32 + 16);
        }
        CP_COMMIT();
    }

    // ---- epilogue ----
    const int g = lane >> 2, t = lane & 3;
    #pragma unroll
    for (int i = 0; i < 4; i++) {
        int r0 = bm + wm * 64 + i * 16 + g;
        int r1 = r0 + 8;
        int d0 = (MODE == 2) ? dest_row(r0) : r0;
        int d1 = (MODE == 2) ? dest_row(r1) : r1;
        #pragma unroll
        for (int j = 0; j < 4; j++) {
            int col = bn + wn * 32 + j * 8 + t * 2;
            float bc0 = bias[col], bc1 = bias[col + 1];
            float v00 = acc[i * 4 + j][0] + bc0;
            float v01 = acc[i * 4 + j][1] + bc1;
            float v10 = acc[i * 4 + j][2] + bc0;
            float v11 = acc[i * 4 + j][3] + bc1;
            if (MODE == 0 || MODE == 1) {
                if (MODE == 1) {
                    v00 = 0.5f * v00 * (1.0f + erff(v00 * 0.70710678118654752f));
                    v01 = 0.5f * v01 * (1.0f + erff(v01 * 0.70710678118654752f));
                    v10 = 0.5f * v10 * (1.0f + erff(v10 * 0.70710678118654752f));
                    v11 = 0.5f * v11 * (1.0f + erff(v11 * 0.70710678118654752f));
                }
                __nv_bfloat162 p0 = __floats2bfloat162_rn(v00, v01);
                __nv_bfloat162 p1 = __floats2bfloat162_rn(v10, v11);
                *(unsigned*)&Cb[(size_t)r0 * N + col] = *(unsigned*)&p0;
                *(unsigned*)&Cb[(size_t)r1 * N + col] = *(unsigned*)&p1;
            } else {
                v00 += res[(size_t)d0 * N + col];
                v01 += res[(size_t)d0 * N + col + 1];
                v10 += res[(size_t)d1 * N + col];
                v11 += res[(size_t)d1 * N + col + 1];
                *(float2*)&Cf[(size_t)d0 * N + col] = make_float2(v00, v01);
                *(float2*)&Cf[(size_t)d1 * N + col] = make_float2(v10, v11);
            }
        }
    }
}

// ---------------------------------------------------------------------------
// Attention: one CTA per (window, head); bf16 qkv in, bf16 out.
// SMEM rows padded to 36 words -> conflict-free column float4 access.
// QK: per (n,m) pair 8x (broadcast q-quad + k-quad) LDS.128, fp32 fma.
// PV: per (n,dquad) item: per m = 1 LDS.32 (S) + 1 LDS.128 (v).
// ---------------------------------------------------------------------------
__global__ void __launch_bounds__(256)
attn_kernel(const __nv_bfloat16* __restrict__ qkv, const float* __restrict__ relt,
            __nv_bfloat16* __restrict__ outp)
{
    int blk  = blockIdx.x;
    int win  = blk / NHEAD;
    int head = blk % NHEAD;

    __shared__ float q [49][36];
    __shared__ float kk[49][36];
    __shared__ float vv[49][36];
    __shared__ float S [49][56];
    __shared__ int   cnt[49];

    int tid = threadIdx.x;

    // load q/k/v (bf16 pairs -> fp32 smem)
    for (int idx = tid; idx < 49 * 16; idx += 256) {
        int n = idx >> 4, dp = idx & 15;
        size_t base = (size_t)(win * 49 + n) * 1152 + head * 32 + dp * 2;
        __nv_bfloat162 hq = *(const __nv_bfloat162*)&qkv[base];
        __nv_bfloat162 hk = *(const __nv_bfloat162*)&qkv[base + 384];
        __nv_bfloat162 hv = *(const __nv_bfloat162*)&qkv[base + 768];
        q [n][dp * 2]     = __low2float(hq)  * ATT_SCALE;
        q [n][dp * 2 + 1] = __high2float(hq) * ATT_SCALE;
        kk[n][dp * 2]     = __low2float(hk);
        kk[n][dp * 2 + 1] = __high2float(hk);
        vv[n][dp * 2]     = __low2float(hv);
        vv[n][dp * 2 + 1] = __high2float(hv);
    }
    if (tid < 49) {
        int wi = win & 63;
        int wh = wi >> 3, ww = wi & 7;
        int i = tid / 7, j = tid % 7;
        int h = wh * 7 + i, w = ww * 7 + j;
        int rh = (h < HH - WSZ)   ? 0 : (h < HH - SHIFT   ? 1 : 2);
        int rw = (w < WWID - WSZ) ? 0 : (w < WWID - SHIFT ? 1 : 2);
        cnt[tid] = rh * 3 + rw;
    }
    __syncthreads();

    // QK^T + bias + mask
    for (int p = tid; p < 49 * 49; p += 256) {
        int n = p / 49, m = p % 49;
        const float4* qr = (const float4*)q[n];
        const float4* kr = (const float4*)kk[m];
        float acc = 0.f;
        #pragma unroll
        for (int c = 0; c < 8; c++) {
            float4 a = qr[c], b = kr[c];
            acc = fmaf(a.x, b.x, acc);
            acc = fmaf(a.y, b.y, acc);
            acc = fmaf(a.z, b.z, acc);
            acc = fmaf(a.w, b.w, acc);
        }
        int di = n / 7 - m / 7 + 6;
        int dj = n % 7 - m % 7 + 6;
        float bias = relt[(di * 13 + dj) * NHEAD + head];
        float mask = (cnt[n] != cnt[m]) ? -100.f : 0.f;
        S[n][m] = acc + bias + mask;
    }
    __syncthreads();

    // softmax (warp per row)
    int wid = tid >> 5, lane = tid & 31;
    for (int n = wid; n < 49; n += 8) {
        float v0 = S[n][lane];
        float v1 = (lane < 17) ? S[n][lane + 32] : -1e30f;
        float mx = fmaxf(v0, v1);
        #pragma unroll
        for (int off = 16; off; off >>= 1)
            mx = fmaxf(mx, __shfl_xor_sync(~0u, mx, off));
        float e0 = expf(v0 - mx);
        float e1 = (lane < 17) ? expf(v1 - mx) : 0.f;
        float sm = e0 + e1;
        #pragma unroll
        for (int off = 16; off; off >>= 1)
            sm += __shfl_xor_sync(~0u, sm, off);
        float inv = 1.f / sm;
        S[n][lane] = e0 * inv;
        if (lane < 17) S[n][lane + 32] = e1 * inv;
    }
    __syncthreads();

    // P @ V, bf16 out
    for (int idx = tid; idx < 49 * 8; idx += 256) {
        int n = idx >> 3, dq = idx & 7;
        float a0 = 0.f, a1 = 0.f, a2 = 0.f, a3 = 0.f;
        #pragma unroll 7
        for (int m = 0; m < 49; m++) {
            float s = S[n][m];
            float4 v = *(const float4*)&vv[m][dq * 4];
            a0 = fmaf(s, v.x, a0);
            a1 = fmaf(s, v.y, a1);
            a2 = fmaf(s, v.z, a2);
            a3 = fmaf(s, v.w, a3);
        }
        __nv_bfloat162 p0 = __floats2bfloat162_rn(a0, a1);
        __nv_bfloat162 p1 = __floats2bfloat162_rn(a2, a3);
        size_t o = (size_t)(win * 49 + n) * 384 + head * 32 + dq * 4;
        *(uint2*)&outp[o] = make_uint2(*(unsigned*)&p0, *(unsigned*)&p1);
    }
}

// ---------------------------------------------------------------------------
// Launch
// ---------------------------------------------------------------------------
extern "C" void kernel_launch(void* const* d_in, const int* in_sizes, int n_in,
                              void* d_out, int out_size)
{
    const float* x      = (const float*)d_in[0];
    const float* ln1_g  = (const float*)d_in[1];
    const float* ln1_b  = (const float*)d_in[2];
    const float* ln2_g  = (const float*)d_in[3];
    const float* ln2_b  = (const float*)d_in[4];
    const float* qkv_w  = (const float*)d_in[5];
    const float* qkv_b  = (const float*)d_in[6];
    const float* proj_w = (const float*)d_in[7];
    const float* proj_b = (const float*)d_in[8];
    const float* mlp_w1 = (const float*)d_in[9];
    const float* mlp_b1 = (const float*)d_in[10];
    const float* mlp_w2 = (const float*)d_in[11];
    const float* mlp_b2 = (const float*)d_in[12];
    const float* relt   = (const float*)d_in[13];
    float* out = (float*)d_out;

    __nv_bfloat16 *wins, *qkvb, *att, *ln2o, *hbuf, *wtq, *wtp, *wt1, *wt2;
    float *x1;
    cudaGetSymbolAddress((void**)&wins, g_wins);
    cudaGetSymbolAddress((void**)&qkvb, g_qkv);
    cudaGetSymbolAddress((void**)&att,  g_att);
    cudaGetSymbolAddress((void**)&x1,   g_x1);
    cudaGetSymbolAddress((void**)&ln2o, g_ln2);
    cudaGetSymbolAddress((void**)&hbuf, g_h);
    cudaGetSymbolAddress((void**)&wtq,  g_wt_qkv);
    cudaGetSymbolAddress((void**)&wtp,  g_wt_proj);
    cudaGetSymbolAddress((void**)&wt1,  g_wt_m1);
    cudaGetSymbolAddress((void**)&wt2,  g_wt_m2);

    // 0. weight transpose + bf16 convert
    transpose_w<<<dim3(384 / 32, 1152 / 32), 256>>>(qkv_w,  wtq, 384, 1152);
    transpose_w<<<dim3(384 / 32,  384 / 32), 256>>>(proj_w, wtp, 384, 384);
    transpose_w<<<dim3(384 / 32, 1536 / 32), 256>>>(mlp_w1, wt1, 384, 1536);
    transpose_w<<<dim3(1536 / 32, 384 / 32), 256>>>(mlp_w2, wt2, 1536, 384);

    // 1. LN1 + cyclic shift + window partition -> bf16
    ln_kernel<<<TOK / 8, 256>>>(x, ln1_g, ln1_b, wins, 1);

    // 2. QKV GEMM: [50176,384] @ [384,1152] -> bf16
    gemm_tc<0><<<dim3(9, TOK / 128), 256>>>(
        wins, wtq, qkv_b, nullptr, nullptr, qkvb, TOK, 1152, 384);

    // 3. Windowed attention -> bf16
    attn_kernel<<<NWIN * NHEAD, 256>>>(qkvb, relt, att);

    // 4. Proj GEMM + window reverse + reverse roll + residual -> fp32
    gemm_tc<2><<<dim3(3, TOK / 128), 256>>>(
        att, wtp, proj_b, x, x1, nullptr, TOK, 384, 384);

    // 5. LN2 -> bf16
    ln_kernel<<<TOK / 8, 256>>>(x1, ln2_g, ln2_b, ln2o, 0);

    // 6. MLP1 + GELU: [50176,384] @ [384,1536] -> bf16
    gemm_tc<1><<<dim3(12, TOK / 128), 256>>>(
        ln2o, wt1, mlp_b1, nullptr, nullptr, hbuf, TOK, 1536, 384);

    // 7. MLP2 + residual: [50176,1536] @ [1536,384] -> d_out
    gemm_tc<3><<<dim3(3, TOK / 128), 256>>>(
        hbuf, wt2, mlp_b2, x1, out, nullptr, TOK, 384, 1536);
}

// round 13
// speedup vs baseline: 1.9139x; 1.0074x over previous
#include <cuda_runtime.h>
#include <cuda_bf16.h>
#include <math.h>
#include <stdint.h>

// ---------------------------------------------------------------------------
// Problem constants
// ---------------------------------------------------------------------------
constexpr int BATCH = 16;
constexpr int HH    = 56;
constexpr int WWID  = 56;
constexpr int CDIM  = 384;
constexpr int NHEAD = 12;
constexpr int WSZ   = 7;
constexpr int SHIFT = 3;
constexpr int NTOK  = 49;
constexpr int NWIN  = BATCH * 64;
constexpr int TOK   = NWIN * NTOK;        // 50176
constexpr float ATT_SCALE = 0.17677669529663687f;
constexpr float LN_EPS    = 1e-3f;

// ---------------------------------------------------------------------------
// Scratch (device globals)
// ---------------------------------------------------------------------------
__device__ __nv_bfloat16 g_wins[TOK * CDIM];
__device__ __nv_bfloat16 g_qkv [TOK * 3 * CDIM];
__device__ __nv_bfloat16 g_att [TOK * CDIM];
__device__ float         g_x1  [TOK * CDIM];
__device__ __nv_bfloat16 g_ln2 [TOK * CDIM];
__device__ __nv_bfloat16 g_h   [TOK * 4 * CDIM];
// transposed bf16 weights [N, K]
__device__ __nv_bfloat16 g_wt_qkv [3 * CDIM * CDIM];
__device__ __nv_bfloat16 g_wt_proj[CDIM * CDIM];
__device__ __nv_bfloat16 g_wt_m1  [4 * CDIM * CDIM];
__device__ __nv_bfloat16 g_wt_m2  [4 * CDIM * CDIM];

// ---------------------------------------------------------------------------
// cp.async helpers
// ---------------------------------------------------------------------------
__device__ __forceinline__ void cp_async16(uint32_t smem, const void* g)
{
    asm volatile("cp.async.cg.shared.global [%0], [%1], 16;"
                 :: "r"(smem), "l"(g));
}
#define CP_COMMIT() asm volatile("cp.async.commit_group;")
#define CP_WAIT(n)  asm volatile("cp.async.wait_group %0;" :: "n"(n))

// ---------------------------------------------------------------------------
// Batched weight transpose + bf16 convert: 4 weights in ONE launch.
// blockIdx.z selects the weight; out-of-range tiles early-exit.
// ---------------------------------------------------------------------------
__global__ void __launch_bounds__(256)
transpose_all(const float* __restrict__ W0, __nv_bfloat16* __restrict__ T0,
              const float* __restrict__ W1, __nv_bfloat16* __restrict__ T1,
              const float* __restrict__ W2, __nv_bfloat16* __restrict__ T2,
              const float* __restrict__ W3, __nv_bfloat16* __restrict__ T3)
{
    const float* W; __nv_bfloat16* T; int K, N;
    switch (blockIdx.z) {
        case 0: W = W0; T = T0; K = 384;  N = 1152; break;
        case 1: W = W1; T = T1; K = 384;  N = 384;  break;
        case 2: W = W2; T = T2; K = 384;  N = 1536; break;
        default:W = W3; T = T3; K = 1536; N = 384;  break;
    }
    int kb = blockIdx.x * 32, nb = blockIdx.y * 32;
    if (kb >= K || nb >= N) return;

    __shared__ float t[32][33];
    int x = threadIdx.x & 31, y = threadIdx.x >> 5;   // 32 x 8
    #pragma unroll
    for (int dy = 0; dy < 32; dy += 8)
        t[y + dy][x] = W[(size_t)(kb + y + dy) * N + nb + x];
    __syncthreads();
    #pragma unroll
    for (int dy = 0; dy < 32; dy += 8)
        T[(size_t)(nb + y + dy) * K + kb + x] = __float2bfloat16(t[x][y + dy]);
}

// ---------------------------------------------------------------------------
// LayerNorm: one WARP per token, 8 tokens per 256-thread block.
// gather=1 fuses roll(-3,+3) + window partition. bf16 output.
// ---------------------------------------------------------------------------
__global__ void __launch_bounds__(256)
ln_kernel(const float* __restrict__ X, const float* __restrict__ gam,
          const float* __restrict__ bet, __nv_bfloat16* __restrict__ Y, int gather)
{
    const int warp = threadIdx.x >> 5, lane = threadIdx.x & 31;
    const int tok = blockIdx.x * 8 + warp;
    int src = tok;
    if (gather) {
        int win = tok / NTOK, n = tok % NTOK;
        int b  = win >> 6, wi = win & 63;
        int wh = wi >> 3,  ww = wi & 7;
        int i  = n / WSZ,  j  = n % WSZ;
        int hs = wh * WSZ + i, ws = ww * WSZ + j;
        int sh = hs + SHIFT; if (sh >= HH)  sh -= HH;
        int sw = ws - SHIFT; if (sw < 0)    sw += WWID;
        src = (b * HH + sh) * WWID + sw;
    }
    const float4* xp = (const float4*)(X + (size_t)src * CDIM);
    float4 v0 = xp[lane], v1 = xp[lane + 32], v2 = xp[lane + 64];

    float s  = v0.x + v0.y + v0.z + v0.w
             + v1.x + v1.y + v1.z + v1.w
             + v2.x + v2.y + v2.z + v2.w;
    float s2 = v0.x * v0.x + v0.y * v0.y + v0.z * v0.z + v0.w * v0.w
             + v1.x * v1.x + v1.y * v1.y + v1.z * v1.z + v1.w * v1.w
             + v2.x * v2.x + v2.y * v2.y + v2.z * v2.z + v2.w * v2.w;
    #pragma unroll
    for (int off = 16; off; off >>= 1) {
        s  += __shfl_xor_sync(~0u, s,  off);
        s2 += __shfl_xor_sync(~0u, s2, off);
    }
    const float mu = s * (1.0f / CDIM);
    const float rs = rsqrtf(s2 * (1.0f / CDIM) - mu * mu + LN_EPS);

    const float4* gp = (const float4*)gam;
    const float4* bp = (const float4*)bet;
    uint2* yp = (uint2*)(Y + (size_t)tok * CDIM);

    #pragma unroll
    for (int q = 0; q < 3; q++) {
        float4 v = (q == 0) ? v0 : (q == 1) ? v1 : v2;
        float4 gg = gp[lane + q * 32];
        float4 bb = bp[lane + q * 32];
        float o0 = (v.x - mu) * rs * gg.x + bb.x;
        float o1 = (v.y - mu) * rs * gg.y + bb.y;
        float o2 = (v.z - mu) * rs * gg.z + bb.z;
        float o3 = (v.w - mu) * rs * gg.w + bb.w;
        __nv_bfloat162 p0 = __floats2bfloat162_rn(o0, o1);
        __nv_bfloat162 p1 = __floats2bfloat162_rn(o2, o3);
        yp[lane + q * 32] = make_uint2(*(unsigned*)&p0, *(unsigned*)&p1);
    }
}

__device__ __forceinline__ int dest_row(int tok)
{
    int win = tok / NTOK, n = tok % NTOK;
    int b  = win >> 6, wi = win & 63;
    int wh = wi >> 3,  ww = wi & 7;
    int i  = n / WSZ,  j  = n % WSZ;
    int hs = wh * WSZ + i, ws = ww * WSZ + j;
    int h = hs + SHIFT; if (h >= HH)   h -= HH;
    int w = ws + SHIFT; if (w >= WWID) w -= WWID;
    return (b * HH + h) * WWID + w;
}

// ---------------------------------------------------------------------------
// bf16 mma.sync GEMM. 128x128 CTA tile, 8 warps (64x32), 4-stage cp.async
// pipeline, BK=32/stage — proven backbone (round 11/12), unchanged.
// MODE 0: +bias -> bf16 Cb          MODE 1: +bias,GELU -> bf16 Cb
// MODE 2: +bias,scatter+res -> fp32 Cf   MODE 3: +bias,+res -> fp32 Cf
// ---------------------------------------------------------------------------
__device__ __forceinline__ void mma_bf16(float* c, const unsigned* a, const unsigned* b)
{
    asm volatile(
        "mma.sync.aligned.m16n8k16.row.col.f32.bf16.bf16.f32 "
        "{%0,%1,%2,%3}, {%4,%5,%6,%7}, {%8,%9}, {%0,%1,%2,%3};"
        : "+f"(c[0]), "+f"(c[1]), "+f"(c[2]), "+f"(c[3])
        : "r"(a[0]), "r"(a[1]), "r"(a[2]), "r"(a[3]), "r"(b[0]), "r"(b[1]));
}

template<int MODE>
__global__ void __launch_bounds__(256)
gemm_tc(const __nv_bfloat16* __restrict__ A, const __nv_bfloat16* __restrict__ Bt,
        const float* __restrict__ bias, const float* __restrict__ res,
        float* __restrict__ Cf, __nv_bfloat16* __restrict__ Cb,
        int M, int N, int K)
{
    constexpr int STAGES = 4;
    __shared__ __align__(16) unsigned As[STAGES][2048];
    __shared__ __align__(16) unsigned Bs[STAGES][2048];

    const int tid  = threadIdx.x;
    const int bm   = blockIdx.y * 128, bn = blockIdx.x * 128;
    const int warp = tid >> 5, lane = tid & 31;
    const int wm   = warp & 1, wn = warp >> 1;       // 2 x 4 warp grid

    const int ma = tid >> 1, ha = tid & 1;
    const __nv_bfloat16* Ag = A + (size_t)(bm + ma) * K + ha * 8;
    const int aOff = ((ma >> 4) * 4 + ((ma >> 3) & 1) + 2 * ha) * 32
                   + (((ma & 7) * 4) ^ (ha << 4));

    const int nb = tid >> 1, hb = tid & 1;
    const __nv_bfloat16* Bg = Bt + (size_t)(bn + nb) * K + hb * 8;
    const int bOff = nb * 8 + ((hb * 4) ^ (((nb >> 2) & 1) << 2));

    const uint32_t aSm = (uint32_t)__cvta_generic_to_shared(&As[0][0]) + aOff * 4;
    const uint32_t bSm = (uint32_t)__cvta_generic_to_shared(&Bs[0][0]) + bOff * 4;

    float acc[16][4];
    #pragma unroll
    for (int i = 0; i < 16; i++)
        #pragma unroll
        for (int j = 0; j < 4; j++) acc[i][j] = 0.f;

    const int NC = K >> 5;

    #pragma unroll
    for (int s = 0; s < STAGES - 1; s++) {
        cp_async16(aSm + s * 8192,        Ag + s * 32);
        cp_async16(aSm + s * 8192 + 4096, Ag + s * 32 + 16);
        cp_async16(bSm + s * 8192,        Bg + s * 32);
        cp_async16(bSm + s * 8192 + 4096, Bg + s * 32 + 16);
        CP_COMMIT();
    }

    for (int c = 0; c < NC; c++) {
        const int st = c & (STAGES - 1);
        CP_WAIT(STAGES - 2);
        __syncthreads();

        #pragma unroll
        for (int sub = 0; sub < 2; sub++) {
            const unsigned* Asb = &As[st][sub * 1024];
            const unsigned* Bsb = &Bs[st][sub * 1024];
            unsigned afr[4][4], bfr[4][2];
            #pragma unroll
            for (int i = 0; i < 4; i++) {
                int blk = (wm * 4 + i) * 4;
                afr[i][0] = Asb[(blk + 0) * 32 + lane];
                afr[i][1] = Asb[(blk + 1) * 32 + lane];
                afr[i][2] = Asb[(blk + 2) * 32 + (lane ^ 16)];
                afr[i][3] = Asb[(blk + 3) * 32 + (lane ^ 16)];
            }
            #pragma unroll
            for (int j = 0; j < 4; j++) {
                int n    = wn * 32 + j * 8 + (lane >> 2);
                int flip = ((n >> 2) & 1) << 2;
                bfr[j][0] = Bsb[n * 8 + ((lane & 3) ^ flip)];
                bfr[j][1] = Bsb[n * 8 + (((lane & 3) + 4) ^ flip)];
            }
            #pragma unroll
            for (int i = 0; i < 4; i++)
                #pragma unroll
                for (int j = 0; j < 4; j++)
                    mma_bf16(acc[i * 4 + j], afr[i], bfr[j]);
        }

        const int nc = c + STAGES - 1;
        if (nc < NC) {
            const int ns = nc & (STAGES - 1);
            cp_async16(aSm + ns * 8192,        Ag + (size_t)nc * 32);
            cp_async16(aSm + ns * 8192 + 4096, Ag + (size_t)nc * 32 + 16);
            cp_async16(bSm + ns * 8192,        Bg + (size_t)nc * 32);
            cp_async16(bSm + ns * 8192 + 4096, Bg + (size_t)nc * 32 + 16);
        }
        CP_COMMIT();
    }

    // ---- epilogue ----
    const int g = lane >> 2, t = lane & 3;
    #pragma unroll
    for (int i = 0; i < 4; i++) {
        int r0 = bm + wm * 64 + i * 16 + g;
        int r1 = r0 + 8;
        int d0 = (MODE == 2) ? dest_row(r0) : r0;
        int d1 = (MODE == 2) ? dest_row(r1) : r1;
        #pragma unroll
        for (int j = 0; j < 4; j++) {
            int col = bn + wn * 32 + j * 8 + t * 2;
            float bc0 = bias[col], bc1 = bias[col + 1];
            float v00 = acc[i * 4 + j][0] + bc0;
            float v01 = acc[i * 4 + j][1] + bc1;
            float v10 = acc[i * 4 + j][2] + bc0;
            float v11 = acc[i * 4 + j][3] + bc1;
            if (MODE == 0 || MODE == 1) {
                if (MODE == 1) {
                    v00 = 0.5f * v00 * (1.0f + erff(v00 * 0.70710678118654752f));
                    v01 = 0.5f * v01 * (1.0f + erff(v01 * 0.70710678118654752f));
                    v10 = 0.5f * v10 * (1.0f + erff(v10 * 0.70710678118654752f));
                    v11 = 0.5f * v11 * (1.0f + erff(v11 * 0.70710678118654752f));
                }
                __nv_bfloat162 p0 = __floats2bfloat162_rn(v00, v01);
                __nv_bfloat162 p1 = __floats2bfloat162_rn(v10, v11);
                *(unsigned*)&Cb[(size_t)r0 * N + col] = *(unsigned*)&p0;
                *(unsigned*)&Cb[(size_t)r1 * N + col] = *(unsigned*)&p1;
            } else {
                v00 += res[(size_t)d0 * N + col];
                v01 += res[(size_t)d0 * N + col + 1];
                v10 += res[(size_t)d1 * N + col];
                v11 += res[(size_t)d1 * N + col + 1];
                *(float2*)&Cf[(size_t)d0 * N + col] = make_float2(v00, v01);
                *(float2*)&Cf[(size_t)d1 * N + col] = make_float2(v10, v11);
            }
        }
    }
}

// ---------------------------------------------------------------------------
// Attention: one CTA per (window, head); bf16 qkv in, bf16 out.
// qkv loads widened to uint4 (16B, 8 bf16) — 196 loads/operand/CTA.
// SMEM rows padded to 36 words -> conflict-free column float4 access.
// ---------------------------------------------------------------------------
__device__ __forceinline__ void unpack8(uint4 h, float* dst, float scale)
{
    const __nv_bfloat162* p = (const __nv_bfloat162*)&h;
    #pragma unroll
    for (int e = 0; e < 4; e++) {
        dst[e * 2]     = __low2float(p[e])  * scale;
        dst[e * 2 + 1] = __high2float(p[e]) * scale;
    }
}

__global__ void __launch_bounds__(256)
attn_kernel(const __nv_bfloat16* __restrict__ qkv, const float* __restrict__ relt,
            __nv_bfloat16* __restrict__ outp)
{
    int blk  = blockIdx.x;
    int win  = blk / NHEAD;
    int head = blk % NHEAD;

    __shared__ float q [49][36];
    __shared__ float kk[49][36];
    __shared__ float vv[49][36];
    __shared__ float S [49][56];
    __shared__ int   cnt[49];

    int tid = threadIdx.x;

    // load q/k/v: 16B (8 bf16) per item, 196 items per operand
    if (tid < 49 * 4) {
        int n = tid >> 2, dc = tid & 3;
        size_t base = (size_t)(win * 49 + n) * 1152 + head * 32 + dc * 8;
        uint4 hq = *(const uint4*)&qkv[base];
        uint4 hk = *(const uint4*)&qkv[base + 384];
        uint4 hv = *(const uint4*)&qkv[base + 768];
        unpack8(hq, &q [n][dc * 8], ATT_SCALE);
        unpack8(hk, &kk[n][dc * 8], 1.0f);
        unpack8(hv, &vv[n][dc * 8], 1.0f);
    }
    if (tid < 49) {
        int wi = win & 63;
        int wh = wi >> 3, ww = wi & 7;
        int i = tid / 7, j = tid % 7;
        int h = wh * 7 + i, w = ww * 7 + j;
        int rh = (h < HH - WSZ)   ? 0 : (h < HH - SHIFT   ? 1 : 2);
        int rw = (w < WWID - WSZ) ? 0 : (w < WWID - SHIFT ? 1 : 2);
        cnt[tid] = rh * 3 + rw;
    }
    __syncthreads();

    // QK^T + bias + mask
    for (int p = tid; p < 49 * 49; p += 256) {
        int n = p / 49, m = p % 49;
        const float4* qr = (const float4*)q[n];
        const float4* kr = (const float4*)kk[m];
        float acc = 0.f;
        #pragma unroll
        for (int c = 0; c < 8; c++) {
            float4 a = qr[c], b = kr[c];
            acc = fmaf(a.x, b.x, acc);
            acc = fmaf(a.y, b.y, acc);
            acc = fmaf(a.z, b.z, acc);
            acc = fmaf(a.w, b.w, acc);
        }
        int di = n / 7 - m / 7 + 6;
        int dj = n % 7 - m % 7 + 6;
        float bias = relt[(di * 13 + dj) * NHEAD + head];
        float mask = (cnt[n] != cnt[m]) ? -100.f : 0.f;
        S[n][m] = acc + bias + mask;
    }
    __syncthreads();

    // softmax (warp per row)
    int wid = tid >> 5, lane = tid & 31;
    for (int n = wid; n < 49; n += 8) {
        float v0 = S[n][lane];
        float v1 = (lane < 17) ? S[n][lane + 32] : -1e30f;
        float mx = fmaxf(v0, v1);
        #pragma unroll
        for (int off = 16; off; off >>= 1)
            mx = fmaxf(mx, __shfl_xor_sync(~0u, mx, off));
        float e0 = expf(v0 - mx);
        float e1 = (lane < 17) ? expf(v1 - mx) : 0.f;
        float sm = e0 + e1;
        #pragma unroll
        for (int off = 16; off; off >>= 1)
            sm += __shfl_xor_sync(~0u, sm, off);
        float inv = 1.f / sm;
        S[n][lane] = e0 * inv;
        if (lane < 17) S[n][lane + 32] = e1 * inv;
    }
    __syncthreads();

    // P @ V, bf16 out
    for (int idx = tid; idx < 49 * 8; idx += 256) {
        int n = idx >> 3, dq = idx & 7;
        float a0 = 0.f, a1 = 0.f, a2 = 0.f, a3 = 0.f;
        #pragma unroll 7
        for (int m = 0; m < 49; m++) {
            float s = S[n][m];
            float4 v = *(const float4*)&vv[m][dq * 4];
            a0 = fmaf(s, v.x, a0);
            a1 = fmaf(s, v.y, a1);
            a2 = fmaf(s, v.z, a2);
            a3 = fmaf(s, v.w, a3);
        }
        __nv_bfloat162 p0 = __floats2bfloat162_rn(a0, a1);
        __nv_bfloat162 p1 = __floats2bfloat162_rn(a2, a3);
        size_t o = (size_t)(win * 49 + n) * 384 + head * 32 + dq * 4;
        *(uint2*)&outp[o] = make_uint2(*(unsigned*)&p0, *(unsigned*)&p1);
    }
}

// ---------------------------------------------------------------------------
// Launch
// ---------------------------------------------------------------------------
extern "C" void kernel_launch(void* const* d_in, const int* in_sizes, int n_in,
                              void* d_out, int out_size)
{
    const float* x      = (const float*)d_in[0];
    const float* ln1_g  = (const float*)d_in[1];
    const float* ln1_b  = (const float*)d_in[2];
    const float* ln2_g  = (const float*)d_in[3];
    const float* ln2_b  = (const float*)d_in[4];
    const float* qkv_w  = (const float*)d_in[5];
    const float* qkv_b  = (const float*)d_in[6];
    const float* proj_w = (const float*)d_in[7];
    const float* proj_b = (const float*)d_in[8];
    const float* mlp_w1 = (const float*)d_in[9];
    const float* mlp_b1 = (const float*)d_in[10];
    const float* mlp_w2 = (const float*)d_in[11];
    const float* mlp_b2 = (const float*)d_in[12];
    const float* relt   = (const float*)d_in[13];
    float* out = (float*)d_out;

    __nv_bfloat16 *wins, *qkvb, *att, *ln2o, *hbuf, *wtq, *wtp, *wt1, *wt2;
    float *x1;
    cudaGetSymbolAddress((void**)&wins, g_wins);
    cudaGetSymbolAddress((void**)&qkvb, g_qkv);
    cudaGetSymbolAddress((void**)&att,  g_att);
    cudaGetSymbolAddress((void**)&x1,   g_x1);
    cudaGetSymbolAddress((void**)&ln2o, g_ln2);
    cudaGetSymbolAddress((void**)&hbuf, g_h);
    cudaGetSymbolAddress((void**)&wtq,  g_wt_qkv);
    cudaGetSymbolAddress((void**)&wtp,  g_wt_proj);
    cudaGetSymbolAddress((void**)&wt1,  g_wt_m1);
    cudaGetSymbolAddress((void**)&wt2,  g_wt_m2);

    // 0. all weight transposes in one launch
    //    grid covers max (K/32=48, N/32=48); out-of-range tiles early-exit
    transpose_all<<<dim3(48, 48, 4), 256>>>(qkv_w, wtq, proj_w, wtp,
                                            mlp_w1, wt1, mlp_w2, wt2);

    // 1. LN1 + cyclic shift + window partition -> bf16
    ln_kernel<<<TOK / 8, 256>>>(x, ln1_g, ln1_b, wins, 1);

    // 2. QKV GEMM: [50176,384] @ [384,1152] -> bf16
    gemm_tc<0><<<dim3(9, TOK / 128), 256>>>(
        wins, wtq, qkv_b, nullptr, nullptr, qkvb, TOK, 1152, 384);

    // 3. Windowed attention -> bf16
    attn_kernel<<<NWIN * NHEAD, 256>>>(qkvb, relt, att);

    // 4. Proj GEMM + window reverse + reverse roll + residual -> fp32
    gemm_tc<2><<<dim3(3, TOK / 128), 256>>>(
        att, wtp, proj_b, x, x1, nullptr, TOK, 384, 384);

    // 5. LN2 -> bf16
    ln_kernel<<<TOK / 8, 256>>>(x1, ln2_g, ln2_b, ln2o, 0);

    // 6. MLP1 + GELU: [50176,384] @ [384,1536] -> bf16
    gemm_tc<1><<<dim3(12, TOK / 128), 256>>>(
        ln2o, wt1, mlp_b1, nullptr, nullptr, hbuf, TOK, 1536, 384);

    // 7. MLP2 + residual: [50176,1536] @ [1536,384] -> d_out
    gemm_tc<3><<<dim3(3, TOK / 128), 256>>>(
        hbuf, wt2, mlp_b2, x1, out, nullptr, TOK, 384, 1536);
}

// round 14
// speedup vs baseline: 2.0179x; 1.0544x over previous
#include <cuda_runtime.h>
#include <cuda_bf16.h>
#include <math.h>
#include <stdint.h>

// ---------------------------------------------------------------------------
// Problem constants
// ---------------------------------------------------------------------------
constexpr int BATCH = 16;
constexpr int HH    = 56;
constexpr int WWID  = 56;
constexpr int CDIM  = 384;
constexpr int NHEAD = 12;
constexpr int WSZ   = 7;
constexpr int SHIFT = 3;
constexpr int NTOK  = 49;
constexpr int NWIN  = BATCH * 64;
constexpr int TOK   = NWIN * NTOK;        // 50176
constexpr float ATT_SCALE = 0.17677669529663687f;
constexpr float LN_EPS    = 1e-3f;

// ---------------------------------------------------------------------------
// Scratch (device globals)
// ---------------------------------------------------------------------------
__device__ __nv_bfloat16 g_wins[TOK * CDIM];
__device__ __nv_bfloat16 g_qkv [TOK * 3 * CDIM];
__device__ __nv_bfloat16 g_att [TOK * CDIM];
__device__ float         g_x1  [TOK * CDIM];
__device__ __nv_bfloat16 g_ln2 [TOK * CDIM];
__device__ __nv_bfloat16 g_h   [TOK * 4 * CDIM];
// transposed bf16 weights [N, K]
__device__ __nv_bfloat16 g_wt_qkv [3 * CDIM * CDIM];
__device__ __nv_bfloat16 g_wt_proj[CDIM * CDIM];
__device__ __nv_bfloat16 g_wt_m1  [4 * CDIM * CDIM];
__device__ __nv_bfloat16 g_wt_m2  [4 * CDIM * CDIM];

// ---------------------------------------------------------------------------
// cp.async helpers
// ---------------------------------------------------------------------------
__device__ __forceinline__ void cp_async16(uint32_t smem, const void* g)
{
    asm volatile("cp.async.cg.shared.global [%0], [%1], 16;"
                 :: "r"(smem), "l"(g));
}
#define CP_COMMIT() asm volatile("cp.async.commit_group;")
#define CP_WAIT(n)  asm volatile("cp.async.wait_group %0;" :: "n"(n))

// ---------------------------------------------------------------------------
// Batched weight transpose + bf16 convert: 4 weights in ONE launch.
// ---------------------------------------------------------------------------
__global__ void __launch_bounds__(256)
transpose_all(const float* __restrict__ W0, __nv_bfloat16* __restrict__ T0,
              const float* __restrict__ W1, __nv_bfloat16* __restrict__ T1,
              const float* __restrict__ W2, __nv_bfloat16* __restrict__ T2,
              const float* __restrict__ W3, __nv_bfloat16* __restrict__ T3)
{
    const float* W; __nv_bfloat16* T; int K, N;
    switch (blockIdx.z) {
        case 0: W = W0; T = T0; K = 384;  N = 1152; break;
        case 1: W = W1; T = T1; K = 384;  N = 384;  break;
        case 2: W = W2; T = T2; K = 384;  N = 1536; break;
        default:W = W3; T = T3; K = 1536; N = 384;  break;
    }
    int kb = blockIdx.x * 32, nb = blockIdx.y * 32;
    if (kb >= K || nb >= N) return;

    __shared__ float t[32][33];
    int x = threadIdx.x & 31, y = threadIdx.x >> 5;   // 32 x 8
    #pragma unroll
    for (int dy = 0; dy < 32; dy += 8)
        t[y + dy][x] = W[(size_t)(kb + y + dy) * N + nb + x];
    __syncthreads();
    #pragma unroll
    for (int dy = 0; dy < 32; dy += 8)
        T[(size_t)(nb + y + dy) * K + kb + x] = __float2bfloat16(t[x][y + dy]);
}

// ---------------------------------------------------------------------------
// LayerNorm: one WARP per token, 8 tokens per 256-thread block.
// gather=1 fuses roll(-3,+3) + window partition. bf16 output.
// ---------------------------------------------------------------------------
__global__ void __launch_bounds__(256)
ln_kernel(const float* __restrict__ X, const float* __restrict__ gam,
          const float* __restrict__ bet, __nv_bfloat16* __restrict__ Y, int gather)
{
    const int warp = threadIdx.x >> 5, lane = threadIdx.x & 31;
    const int tok = blockIdx.x * 8 + warp;
    int src = tok;
    if (gather) {
        int win = tok / NTOK, n = tok % NTOK;
        int b  = win >> 6, wi = win & 63;
        int wh = wi >> 3,  ww = wi & 7;
        int i  = n / WSZ,  j  = n % WSZ;
        int hs = wh * WSZ + i, ws = ww * WSZ + j;
        int sh = hs + SHIFT; if (sh >= HH)  sh -= HH;
        int sw = ws - SHIFT; if (sw < 0)    sw += WWID;
        src = (b * HH + sh) * WWID + sw;
    }
    const float4* xp = (const float4*)(X + (size_t)src * CDIM);
    float4 v0 = xp[lane], v1 = xp[lane + 32], v2 = xp[lane + 64];

    float s  = v0.x + v0.y + v0.z + v0.w
             + v1.x + v1.y + v1.z + v1.w
             + v2.x + v2.y + v2.z + v2.w;
    float s2 = v0.x * v0.x + v0.y * v0.y + v0.z * v0.z + v0.w * v0.w
             + v1.x * v1.x + v1.y * v1.y + v1.z * v1.z + v1.w * v1.w
             + v2.x * v2.x + v2.y * v2.y + v2.z * v2.z + v2.w * v2.w;
    #pragma unroll
    for (int off = 16; off; off >>= 1) {
        s  += __shfl_xor_sync(~0u, s,  off);
        s2 += __shfl_xor_sync(~0u, s2, off);
    }
    const float mu = s * (1.0f / CDIM);
    const float rs = rsqrtf(s2 * (1.0f / CDIM) - mu * mu + LN_EPS);

    const float4* gp = (const float4*)gam;
    const float4* bp = (const float4*)bet;
    uint2* yp = (uint2*)(Y + (size_t)tok * CDIM);

    #pragma unroll
    for (int q = 0; q < 3; q++) {
        float4 v = (q == 0) ? v0 : (q == 1) ? v1 : v2;
        float4 gg = gp[lane + q * 32];
        float4 bb = bp[lane + q * 32];
        float o0 = (v.x - mu) * rs * gg.x + bb.x;
        float o1 = (v.y - mu) * rs * gg.y + bb.y;
        float o2 = (v.z - mu) * rs * gg.z + bb.z;
        float o3 = (v.w - mu) * rs * gg.w + bb.w;
        __nv_bfloat162 p0 = __floats2bfloat162_rn(o0, o1);
        __nv_bfloat162 p1 = __floats2bfloat162_rn(o2, o3);
        yp[lane + q * 32] = make_uint2(*(unsigned*)&p0, *(unsigned*)&p1);
    }
}

__device__ __forceinline__ int dest_row(int tok)
{
    int win = tok / NTOK, n = tok % NTOK;
    int b  = win >> 6, wi = win & 63;
    int wh = wi >> 3,  ww = wi & 7;
    int i  = n / WSZ,  j  = n % WSZ;
    int hs = wh * WSZ + i, ws = ww * WSZ + j;
    int h = hs + SHIFT; if (h >= HH)   h -= HH;
    int w = ws + SHIFT; if (w >= WWID) w -= WWID;
    return (b * HH + h) * WWID + w;
}

// ---------------------------------------------------------------------------
// bf16 mma.sync GEMM. 128x128 CTA tile, 8 warps (64x32), 4-stage cp.async
// pipeline, BK=32/stage — proven backbone, unchanged.
// ---------------------------------------------------------------------------
__device__ __forceinline__ void mma_bf16(float* c, const unsigned* a, const unsigned* b)
{
    asm volatile(
        "mma.sync.aligned.m16n8k16.row.col.f32.bf16.bf16.f32 "
        "{%0,%1,%2,%3}, {%4,%5,%6,%7}, {%8,%9}, {%0,%1,%2,%3};"
        : "+f"(c[0]), "+f"(c[1]), "+f"(c[2]), "+f"(c[3])
        : "r"(a[0]), "r"(a[1]), "r"(a[2]), "r"(a[3]), "r"(b[0]), "r"(b[1]));
}

template<int MODE>
__global__ void __launch_bounds__(256)
gemm_tc(const __nv_bfloat16* __restrict__ A, const __nv_bfloat16* __restrict__ Bt,
        const float* __restrict__ bias, const float* __restrict__ res,
        float* __restrict__ Cf, __nv_bfloat16* __restrict__ Cb,
        int M, int N, int K)
{
    constexpr int STAGES = 4;
    __shared__ __align__(16) unsigned As[STAGES][2048];
    __shared__ __align__(16) unsigned Bs[STAGES][2048];

    const int tid  = threadIdx.x;
    const int bm   = blockIdx.y * 128, bn = blockIdx.x * 128;
    const int warp = tid >> 5, lane = tid & 31;
    const int wm   = warp & 1, wn = warp >> 1;       // 2 x 4 warp grid

    const int ma = tid >> 1, ha = tid & 1;
    const __nv_bfloat16* Ag = A + (size_t)(bm + ma) * K + ha * 8;
    const int aOff = ((ma >> 4) * 4 + ((ma >> 3) & 1) + 2 * ha) * 32
                   + (((ma & 7) * 4) ^ (ha << 4));

    const int nb = tid >> 1, hb = tid & 1;
    const __nv_bfloat16* Bg = Bt + (size_t)(bn + nb) * K + hb * 8;
    const int bOff = nb * 8 + ((hb * 4) ^ (((nb >> 2) & 1) << 2));

    const uint32_t aSm = (uint32_t)__cvta_generic_to_shared(&As[0][0]) + aOff * 4;
    const uint32_t bSm = (uint32_t)__cvta_generic_to_shared(&Bs[0][0]) + bOff * 4;

    float acc[16][4];
    #pragma unroll
    for (int i = 0; i < 16; i++)
        #pragma unroll
        for (int j = 0; j < 4; j++) acc[i][j] = 0.f;

    const int NC = K >> 5;

    #pragma unroll
    for (int s = 0; s < STAGES - 1; s++) {
        cp_async16(aSm + s * 8192,        Ag + s * 32);
        cp_async16(aSm + s * 8192 + 4096, Ag + s * 32 + 16);
        cp_async16(bSm + s * 8192,        Bg + s * 32);
        cp_async16(bSm + s * 8192 + 4096, Bg + s * 32 + 16);
        CP_COMMIT();
    }

    for (int c = 0; c < NC; c++) {
        const int st = c & (STAGES - 1);
        CP_WAIT(STAGES - 2);
        __syncthreads();

        #pragma unroll
        for (int sub = 0; sub < 2; sub++) {
            const unsigned* Asb = &As[st][sub * 1024];
            const unsigned* Bsb = &Bs[st][sub * 1024];
            unsigned afr[4][4], bfr[4][2];
            #pragma unroll
            for (int i = 0; i < 4; i++) {
                int blk = (wm * 4 + i) * 4;
                afr[i][0] = Asb[(blk + 0) * 32 + lane];
                afr[i][1] = Asb[(blk + 1) * 32 + lane];
                afr[i][2] = Asb[(blk + 2) * 32 + (lane ^ 16)];
                afr[i][3] = Asb[(blk + 3) * 32 + (lane ^ 16)];
            }
            #pragma unroll
            for (int j = 0; j < 4; j++) {
                int n    = wn * 32 + j * 8 + (lane >> 2);
                int flip = ((n >> 2) & 1) << 2;
                bfr[j][0] = Bsb[n * 8 + ((lane & 3) ^ flip)];
                bfr[j][1] = Bsb[n * 8 + (((lane & 3) + 4) ^ flip)];
            }
            #pragma unroll
            for (int i = 0; i < 4; i++)
                #pragma unroll
                for (int j = 0; j < 4; j++)
                    mma_bf16(acc[i * 4 + j], afr[i], bfr[j]);
        }

        const int nc = c + STAGES - 1;
        if (nc < NC) {
            const int ns = nc & (STAGES - 1);
            cp_async16(aSm + ns * 8192,        Ag + (size_t)nc * 32);
            cp_async16(aSm + ns * 8192 + 4096, Ag + (size_t)nc * 32 + 16);
            cp_async16(bSm + ns * 8192,        Bg + (size_t)nc * 32);
            cp_async16(bSm + ns * 8192 + 4096, Bg + (size_t)nc * 32 + 16);
        }
        CP_COMMIT();
    }

    // ---- epilogue ----
    const int g = lane >> 2, t = lane & 3;
    #pragma unroll
    for (int i = 0; i < 4; i++) {
        int r0 = bm + wm * 64 + i * 16 + g;
        int r1 = r0 + 8;
        int d0 = (MODE == 2) ? dest_row(r0) : r0;
        int d1 = (MODE == 2) ? dest_row(r1) : r1;
        #pragma unroll
        for (int j = 0; j < 4; j++) {
            int col = bn + wn * 32 + j * 8 + t * 2;
            float bc0 = bias[col], bc1 = bias[col + 1];
            float v00 = acc[i * 4 + j][0] + bc0;
            float v01 = acc[i * 4 + j][1] + bc1;
            float v10 = acc[i * 4 + j][2] + bc0;
            float v11 = acc[i * 4 + j][3] + bc1;
            if (MODE == 0 || MODE == 1) {
                if (MODE == 1) {
                    v00 = 0.5f * v00 * (1.0f + erff(v00 * 0.70710678118654752f));
                    v01 = 0.5f * v01 * (1.0f + erff(v01 * 0.70710678118654752f));
                    v10 = 0.5f * v10 * (1.0f + erff(v10 * 0.70710678118654752f));
                    v11 = 0.5f * v11 * (1.0f + erff(v11 * 0.70710678118654752f));
                }
                __nv_bfloat162 p0 = __floats2bfloat162_rn(v00, v01);
                __nv_bfloat162 p1 = __floats2bfloat162_rn(v10, v11);
                *(unsigned*)&Cb[(size_t)r0 * N + col] = *(unsigned*)&p0;
                *(unsigned*)&Cb[(size_t)r1 * N + col] = *(unsigned*)&p1;
            } else {
                v00 += res[(size_t)d0 * N + col];
                v01 += res[(size_t)d0 * N + col + 1];
                v10 += res[(size_t)d1 * N + col];
                v11 += res[(size_t)d1 * N + col + 1];
                *(float2*)&Cf[(size_t)d0 * N + col] = make_float2(v00, v01);
                *(float2*)&Cf[(size_t)d1 * N + col] = make_float2(v10, v11);
            }
        }
    }
}

// ---------------------------------------------------------------------------
// Attention: one CTA per (window, head); bf16 qkv in, bf16 out.
// QK with K-in-registers: 4 groups x 64 threads; each thread pins its k-row
// (8 float4) in registers; q-quad reads are warp-broadcast LDS.128.
// QK wavefronts ~1040/CTA vs ~4800 in the all-SMEM form. Same FMA order ->
// bitwise-identical S. Softmax / PV unchanged.
// ---------------------------------------------------------------------------
__device__ __forceinline__ void unpack8(uint4 h, float* dst, float scale)
{
    const __nv_bfloat162* p = (const __nv_bfloat162*)&h;
    #pragma unroll
    for (int e = 0; e < 4; e++) {
        dst[e * 2]     = __low2float(p[e])  * scale;
        dst[e * 2 + 1] = __high2float(p[e]) * scale;
    }
}

__global__ void __launch_bounds__(256)
attn_kernel(const __nv_bfloat16* __restrict__ qkv, const float* __restrict__ relt,
            __nv_bfloat16* __restrict__ outp)
{
    int blk  = blockIdx.x;
    int win  = blk / NHEAD;
    int head = blk % NHEAD;

    __shared__ float q [49][36];
    __shared__ float kk[49][36];
    __shared__ float vv[49][36];
    __shared__ float S [49][56];
    __shared__ int   cnt[49];

    int tid = threadIdx.x;

    // load q/k/v: 16B (8 bf16) per item, 196 items per operand
    if (tid < 49 * 4) {
        int n = tid >> 2, dc = tid & 3;
        size_t base = (size_t)(win * 49 + n) * 1152 + head * 32 + dc * 8;
        uint4 hq = *(const uint4*)&qkv[base];
        uint4 hk = *(const uint4*)&qkv[base + 384];
        uint4 hv = *(const uint4*)&qkv[base + 768];
        unpack8(hq, &q [n][dc * 8], ATT_SCALE);
        unpack8(hk, &kk[n][dc * 8], 1.0f);
        unpack8(hv, &vv[n][dc * 8], 1.0f);
    }
    if (tid < 49) {
        int wi = win & 63;
        int wh = wi >> 3, ww = wi & 7;
        int i = tid / 7, j = tid % 7;
        int h = wh * 7 + i, w = ww * 7 + j;
        int rh = (h < HH - WSZ)   ? 0 : (h < HH - SHIFT   ? 1 : 2);
        int rw = (w < WWID - WSZ) ? 0 : (w < WWID - SHIFT ? 1 : 2);
        cnt[tid] = rh * 3 + rw;
    }
    __syncthreads();

    // ---- QK^T + bias + mask : K pinned in registers ----
    {
        const int grp = tid >> 6;          // 4 groups
        const int m   = tid & 63;          // lane's key index (valid if < 49)
        const bool mv = (m < 49);

        float4 kr[8];
        int cm = 0;
        if (mv) {
            const float4* krow = (const float4*)kk[m];
            #pragma unroll
            for (int c = 0; c < 8; c++) kr[c] = krow[c];
            cm = cnt[m];
        }

        for (int n = grp; n < 49; n += 4) {
            const float4* qr = (const float4*)q[n];
            float acc = 0.f;
            #pragma unroll
            for (int c = 0; c < 8; c++) {
                float4 a = qr[c];          // warp-broadcast LDS.128
                acc = fmaf(a.x, kr[c].x, acc);
                acc = fmaf(a.y, kr[c].y, acc);
                acc = fmaf(a.z, kr[c].z, acc);
                acc = fmaf(a.w, kr[c].w, acc);
            }
            if (mv) {
                int di = n / 7 - m / 7 + 6;
                int dj = n % 7 - m % 7 + 6;
                float bias = relt[(di * 13 + dj) * NHEAD + head];
                float mask = (cnt[n] != cm) ? -100.f : 0.f;
                S[n][m] = acc + bias + mask;
            }
        }
    }
    __syncthreads();

    // softmax (warp per row)
    int wid = tid >> 5, lane = tid & 31;
    for (int n = wid; n < 49; n += 8) {
        float v0 = S[n][lane];
        float v1 = (lane < 17) ? S[n][lane + 32] : -1e30f;
        float mx = fmaxf(v0, v1);
        #pragma unroll
        for (int off = 16; off; off >>= 1)
            mx = fmaxf(mx, __shfl_xor_sync(~0u, mx, off));
        float e0 = expf(v0 - mx);
        float e1 = (lane < 17) ? expf(v1 - mx) : 0.f;
        float sm = e0 + e1;
        #pragma unroll
        for (int off = 16; off; off >>= 1)
            sm += __shfl_xor_sync(~0u, sm, off);
        float inv = 1.f / sm;
        S[n][lane] = e0 * inv;
        if (lane < 17) S[n][lane + 32] = e1 * inv;
    }
    __syncthreads();

    // P @ V, bf16 out
    for (int idx = tid; idx < 49 * 8; idx += 256) {
        int n = idx >> 3, dq = idx & 7;
        float a0 = 0.f, a1 = 0.f, a2 = 0.f, a3 = 0.f;
        #pragma unroll 7
        for (int m = 0; m < 49; m++) {
            float s = S[n][m];
            float4 v = *(const float4*)&vv[m][dq * 4];
            a0 = fmaf(s, v.x, a0);
            a1 = fmaf(s, v.y, a1);
            a2 = fmaf(s, v.z, a2);
            a3 = fmaf(s, v.w, a3);
        }
        __nv_bfloat162 p0 = __floats2bfloat162_rn(a0, a1);
        __nv_bfloat162 p1 = __floats2bfloat162_rn(a2, a3);
        size_t o = (size_t)(win * 49 + n) * 384 + head * 32 + dq * 4;
        *(uint2*)&outp[o] = make_uint2(*(unsigned*)&p0, *(unsigned*)&p1);
    }
}

// ---------------------------------------------------------------------------
// Launch
// ---------------------------------------------------------------------------
extern "C" void kernel_launch(void* const* d_in, const int* in_sizes, int n_in,
                              void* d_out, int out_size)
{
    const float* x      = (const float*)d_in[0];
    const float* ln1_g  = (const float*)d_in[1];
    const float* ln1_b  = (const float*)d_in[2];
    const float* ln2_g  = (const float*)d_in[3];
    const float* ln2_b  = (const float*)d_in[4];
    const float* qkv_w  = (const float*)d_in[5];
    const float* qkv_b  = (const float*)d_in[6];
    const float* proj_w = (const float*)d_in[7];
    const float* proj_b = (const float*)d_in[8];
    const float* mlp_w1 = (const float*)d_in[9];
    const float* mlp_b1 = (const float*)d_in[10];
    const float* mlp_w2 = (const float*)d_in[11];
    const float* mlp_b2 = (const float*)d_in[12];
    const float* relt   = (const float*)d_in[13];
    float* out = (float*)d_out;

    __nv_bfloat16 *wins, *qkvb, *att, *ln2o, *hbuf, *wtq, *wtp, *wt1, *wt2;
    float *x1;
    cudaGetSymbolAddress((void**)&wins, g_wins);
    cudaGetSymbolAddress((void**)&qkvb, g_qkv);
    cudaGetSymbolAddress((void**)&att,  g_att);
    cudaGetSymbolAddress((void**)&x1,   g_x1);
    cudaGetSymbolAddress((void**)&ln2o, g_ln2);
    cudaGetSymbolAddress((void**)&hbuf, g_h);
    cudaGetSymbolAddress((void**)&wtq,  g_wt_qkv);
    cudaGetSymbolAddress((void**)&wtp,  g_wt_proj);
    cudaGetSymbolAddress((void**)&wt1,  g_wt_m1);
    cudaGetSymbolAddress((void**)&wt2,  g_wt_m2);

    // 0. all weight transposes in one launch
    transpose_all<<<dim3(48, 48, 4), 256>>>(qkv_w, wtq, proj_w, wtp,
                                            mlp_w1, wt1, mlp_w2, wt2);

    // 1. LN1 + cyclic shift + window partition -> bf16
    ln_kernel<<<TOK / 8, 256>>>(x, ln1_g, ln1_b, wins, 1);

    // 2. QKV GEMM: [50176,384] @ [384,1152] -> bf16
    gemm_tc<0><<<dim3(9, TOK / 128), 256>>>(
        wins, wtq, qkv_b, nullptr, nullptr, qkvb, TOK, 1152, 384);

    // 3. Windowed attention -> bf16
    attn_kernel<<<NWIN * NHEAD, 256>>>(qkvb, relt, att);

    // 4. Proj GEMM + window reverse + reverse roll + residual -> fp32
    gemm_tc<2><<<dim3(3, TOK / 128), 256>>>(
        att, wtp, proj_b, x, x1, nullptr, TOK, 384, 384);

    // 5. LN2 -> bf16
    ln_kernel<<<TOK / 8, 256>>>(x1, ln2_g, ln2_b, ln2o, 0);

    // 6. MLP1 + GELU: [50176,384] @ [384,1536] -> bf16
    gemm_tc<1><<<dim3(12, TOK / 128), 256>>>(
        ln2o, wt1, mlp_b1, nullptr, nullptr, hbuf, TOK, 1536, 384);

    // 7. MLP2 + residual: [50176,1536] @ [1536,384] -> d_out
    gemm_tc<3><<<dim3(3, TOK / 128), 256>>>(
        hbuf, wt2, mlp_b2, x1, out, nullptr, TOK, 384, 1536);
}